// round 4
// baseline (speedup 1.0000x reference)
#include <cuda_runtime.h>
#include <math.h>

#define N_NODES 20000
#define NE      320000
#define ET      (NE + N_NODES)
#define HEADS   4

// ---------------- scratch (device globals; no allocation) ----------------
static __device__ float g_xw0[(size_t)N_NODES * 256];
static __device__ float g_h0 [(size_t)N_NODES * 256];
static __device__ float g_xw1[(size_t)N_NODES * 128];
static __device__ float g_h1 [(size_t)N_NODES * 128];
static __device__ float g_z0 [(size_t)N_NODES * 128];
static __device__ float g_z1 [(size_t)N_NODES * 64];
static __device__ float g_s  [N_NODES * 4];
static __device__ float g_d  [N_NODES * 4];
static __device__ int   g_cnt[N_NODES];
static __device__ int   g_cur[N_NODES];
static __device__ int   g_off[N_NODES + 1];
static __device__ int   g_csr[ET];

// ---------------- helpers ----------------
__device__ __forceinline__ float softplusf(float x) {
    return x > 20.f ? x : log1pf(__expf(x));
}

__device__ __forceinline__ float u64lo(unsigned long long u) {
    return __uint_as_float((unsigned)(u & 0xffffffffu));
}
__device__ __forceinline__ float u64hi(unsigned long long u) {
    return __uint_as_float((unsigned)(u >> 32));
}

__device__ __forceinline__ void edge_uv(const int* __restrict__ ei, int e, int& u, int& v) {
    if (e < NE) { u = ei[e]; v = ei[NE + e]; }
    else        { u = v = e - NE; }   // self loops appended
}

// ================= CSR build (group edges by dst) =================
__global__ void zero_cnt_kernel(int* __restrict__ cnt) {
    int i = blockIdx.x * blockDim.x + threadIdx.x;
    if (i < N_NODES) cnt[i] = 0;
}

__global__ void hist_kernel(const int* __restrict__ ei, int* __restrict__ cnt) {
    int e = blockIdx.x * blockDim.x + threadIdx.x;
    if (e >= ET) return;
    int u, v; edge_uv(ei, e, u, v);
    (void)u;
    atomicAdd(&cnt[v], 1);
}

// single-block exclusive scan of cnt -> off; zero cur
__global__ void scan_kernel(const int* __restrict__ cnt, int* __restrict__ off,
                            int* __restrict__ cur) {
    const int CHUNK = (N_NODES + 1023) / 1024;   // 20
    __shared__ int ts[1024];
    int tid = threadIdx.x;
    int base = tid * CHUNK;
    int s = 0;
    for (int i = 0; i < CHUNK; i++) {
        int idx = base + i;
        if (idx < N_NODES) s += cnt[idx];
    }
    ts[tid] = s;
    __syncthreads();
    for (int o = 1; o < 1024; o <<= 1) {
        int v = (tid >= o) ? ts[tid - o] : 0;
        __syncthreads();
        ts[tid] += v;
        __syncthreads();
    }
    int run = (tid > 0) ? ts[tid - 1] : 0;
    for (int i = 0; i < CHUNK; i++) {
        int idx = base + i;
        if (idx < N_NODES) {
            off[idx] = run;
            run += cnt[idx];
            cur[idx] = 0;
        }
    }
    if (tid == (N_NODES - 1) / CHUNK) off[N_NODES] = run;
}

__global__ void scatter_kernel(const int* __restrict__ ei, const int* __restrict__ off,
                               int* __restrict__ cur, int* __restrict__ csr) {
    int e = blockIdx.x * blockDim.x + threadIdx.x;
    if (e >= ET) return;
    int u, v; edge_uv(ei, e, u, v);
    int pos = off[v] + atomicAdd(&cur[v], 1);
    csr[pos] = u;
}

// ================= packed f32x2 GEMM: C = A[n,K] * W[M,K]^T (+bias, act) ==========
// mode: 0 = plain, 1 = softplus, 2 = softplus+clip(0.1,1000) transposed [M,n],
//       3 = softplus transposed [M,n]
// Thread tile TM x TN = 8x8; rows packed in pairs (fma.rn.f32x2); B pre-duplicated in smem.
template<int BM, int BN, int BK, int TM, int TN>
__global__ void __launch_bounds__((BM/TM)*(BN/TN))
gemm2_kernel(const float* __restrict__ A, const float* __restrict__ W,
             const float* __restrict__ bias, float* __restrict__ C,
             int n, int K, int M, int mode) {
    constexpr int BX = BN / TN;          // threads.x
    constexpr int BY = BM / TM;          // threads.y
    constexpr int NT = BX * BY;
    constexpr int KQ = BK / 4;           // float4 loads per row
    constexpr int ASTR = BM + 4;         // floats (keeps 16B alignment: (BM+4)*4 % 16 == 0)
    constexpr int BSTR = BN + 1;         // float2 units

    __shared__ __align__(16) float  Ast[BK * ASTR];   // A transposed: [k][row]
    __shared__ __align__(16) float2 Bsd[BK * BSTR];   // B duplicated: [k][col] = {w,w}

    const int bi = blockIdx.x * BM;
    const int bj = blockIdx.y * BN;
    const int tx = threadIdx.x, ty = threadIdx.y;
    const int t = ty * BX + tx;

    unsigned long long acc[TM / 2][TN];
#pragma unroll
    for (int r = 0; r < TM / 2; r++)
#pragma unroll
        for (int c = 0; c < TN; c++) acc[r][c] = 0ull;

    for (int k0 = 0; k0 < K; k0 += BK) {
        // ---- load A panel (transpose into Ast) ----
        constexpr int AF4 = BM * BK / 4;
#pragma unroll
        for (int i = t; i < AF4; i += NT) {
            int row = i / KQ;
            int kq  = i % KQ;
            float4 v = make_float4(0.f, 0.f, 0.f, 0.f);
            if (bi + row < n)
                v = *(const float4*)(A + (size_t)(bi + row) * K + k0 + kq * 4);
            Ast[(4 * kq + 0) * ASTR + row] = v.x;
            Ast[(4 * kq + 1) * ASTR + row] = v.y;
            Ast[(4 * kq + 2) * ASTR + row] = v.z;
            Ast[(4 * kq + 3) * ASTR + row] = v.w;
        }
        // ---- load B panel (duplicate into Bsd) ----
        constexpr int BF4 = BN * BK / 4;
#pragma unroll
        for (int i = t; i < BF4; i += NT) {
            int col = i / KQ;
            int kq  = i % KQ;
            float4 v = *(const float4*)(W + (size_t)(bj + col) * K + k0 + kq * 4);
            Bsd[(4 * kq + 0) * BSTR + col] = make_float2(v.x, v.x);
            Bsd[(4 * kq + 1) * BSTR + col] = make_float2(v.y, v.y);
            Bsd[(4 * kq + 2) * BSTR + col] = make_float2(v.z, v.z);
            Bsd[(4 * kq + 3) * BSTR + col] = make_float2(v.w, v.w);
        }
        __syncthreads();

#pragma unroll
        for (int kk = 0; kk < BK; kk++) {
            const float* ar = &Ast[kk * ASTR + ty * TM];
            ulonglong2 a01 = *(const ulonglong2*)(ar);
            ulonglong2 a23 = *(const ulonglong2*)(ar + 4);
            unsigned long long av[4] = {a01.x, a01.y, a23.x, a23.y};
            unsigned long long bv[TN];
#pragma unroll
            for (int c = 0; c < TN; c++)
                bv[c] = *(const unsigned long long*)&Bsd[kk * BSTR + tx + BX * c];
#pragma unroll
            for (int r = 0; r < TM / 2; r++)
#pragma unroll
                for (int c = 0; c < TN; c++)
                    asm("fma.rn.f32x2 %0, %1, %2, %0;"
                        : "+l"(acc[r][c]) : "l"(av[r]), "l"(bv[c]));
        }
        __syncthreads();
    }

    // ---- epilogue ----
#pragma unroll
    for (int r = 0; r < TM / 2; r++) {
        int i0 = bi + ty * TM + 2 * r;
#pragma unroll
        for (int c = 0; c < TN; c++) {
            int j = bj + tx + BX * c;
            float v0 = u64lo(acc[r][c]);
            float v1 = u64hi(acc[r][c]);
            float b = bias ? bias[j] : 0.f;
            v0 += b; v1 += b;
            if (mode != 0) { v0 = softplusf(v0); v1 = softplusf(v1); }
            if (mode == 2) {
                v0 = fminf(fmaxf(v0, 0.1f), 1000.f);
                v1 = fminf(fmaxf(v1, 0.1f), 1000.f);
            }
            if (mode >= 2) {
                if (i0 + 1 < n) *(float2*)&C[(size_t)j * n + i0] = make_float2(v0, v1);
                else if (i0 < n) C[(size_t)j * n + i0] = v0;
            } else {
                if (i0 < n)     C[(size_t)i0 * M + j] = v0;
                if (i0 + 1 < n) C[(size_t)(i0 + 1) * M + j] = v1;
            }
        }
    }
}

// ---------------- attention source/dest scores: one warp per (node, head) ----------------
__global__ void sd_kernel(const float* __restrict__ xw,
                          const float* __restrict__ asrc, const float* __restrict__ adst,
                          float* __restrict__ s, float* __restrict__ d, int C) {
    int warp = (blockIdx.x * blockDim.x + threadIdx.x) >> 5;
    int lane = threadIdx.x & 31;
    if (warp >= N_NODES * HEADS) return;
    int node = warp >> 2, h = warp & 3;
    const float* base = xw + (size_t)node * HEADS * C + h * C;
    float ss = 0.f, dd = 0.f;
    for (int c = lane; c < C; c += 32) {
        float v = base[c];
        ss += v * asrc[h * C + c];
        dd += v * adst[h * C + c];
    }
#pragma unroll
    for (int o = 16; o; o >>= 1) {
        ss += __shfl_down_sync(0xffffffffu, ss, o);
        dd += __shfl_down_sync(0xffffffffu, dd, o);
    }
    if (lane == 0) { s[warp] = ss; d[warp] = dd; }
}

// ================= fused per-node GAT softmax + aggregation =================
template <int C>
__global__ void gat_kernel(const int* __restrict__ csr, const int* __restrict__ off,
                           const float* __restrict__ s, const float* __restrict__ d,
                           const float* __restrict__ xw, const float* __restrict__ bias,
                           float* __restrict__ out) {
    constexpr int HC = 4 * C;
    const int v = blockIdx.x;
    const int tid = threadIdx.x;
    const int h = tid / C;
    const int c = tid - h * C;           // in-head lane 0..C-1
    const int beg = off[v], end = off[v + 1];

    __shared__ float red[HC];
    __shared__ float mh[4], inv[4];

    const float dv = d[v * 4 + h];

    // pass 1: per-head max of leaky(s[u]+d[v]) — each head group covers all edges
    float lmax = -INFINITY;
    for (int j = beg + c; j < end; j += C) {
        int u = csr[j];
        float e = s[u * 4 + h] + dv;
        e = e > 0.f ? e : 0.2f * e;
        lmax = fmaxf(lmax, e);
    }
    red[tid] = lmax;
    __syncthreads();
    if (tid < 4) {
        float m = -INFINITY;
        for (int i = 0; i < C; i++) m = fmaxf(m, red[tid * C + i]);
        mh[tid] = m;
    }
    __syncthreads();
    const float m = mh[h];

    // pass 2: per-head sum of exp(e - m)
    float lsum = 0.f;
    for (int j = beg + c; j < end; j += C) {
        int u = csr[j];
        float e = s[u * 4 + h] + dv;
        e = e > 0.f ? e : 0.2f * e;
        lsum += __expf(e - m);
    }
    red[tid] = lsum;
    __syncthreads();
    if (tid < 4) {
        float sm = 0.f;
        for (int i = 0; i < C; i++) sm += red[tid * C + i];
        inv[tid] = 1.f / (sm + 1e-16f);
    }
    __syncthreads();
    const float invden = inv[h];

    // pass 3: weighted aggregation (coalesced xw row per edge)
    float acc = 0.f;
    for (int j = beg; j < end; j++) {
        int u = csr[j];
        float e = s[u * 4 + h] + dv;
        e = e > 0.f ? e : 0.2f * e;
        float w = __expf(e - m) * invden;
        acc = fmaf(w, xw[(size_t)u * HC + tid], acc);
    }
    out[(size_t)v * HC + tid] = acc + bias[tid];
}

// ---------------- fused kl_fix + theta ----------------
// l_in holds raw softplus; writes corrected l and theta.
__global__ void theta_kernel(const float* __restrict__ k, float* __restrict__ l,
                             const float* __restrict__ eps, float* __restrict__ th, int ZN) {
    int i = blockIdx.x * blockDim.x + threadIdx.x;
    if (i >= ZN) return;
    float kk = k[i];
    float invk = 1.f / kk;
    float ll = fmaxf(l[i], 2.2e-10f) * expf(-lgammaf(1.f + invk));
    l[i] = ll;
    float acc = 0.f;
#pragma unroll
    for (int s = 0; s < 10; s++) {
        float ep = eps[(size_t)s * ZN + i];
        float t = fmaxf(1.f - ep, 2.2e-10f);
        float nl = -__logf(t);
        acc += __powf(nl, invk);
    }
    float theta = ll * acc * 0.1f;
    th[i] = fminf(fmaxf(theta, 2.2e-10f), 1000.f);
}

// ---------------- host launch ----------------
template <typename T>
static float* symaddrf(T& sym) { void* p = nullptr; cudaGetSymbolAddress(&p, sym); return (float*)p; }
template <typename T>
static int* symaddri(T& sym) { void* p = nullptr; cudaGetSymbolAddress(&p, sym); return (int*)p; }

extern "C" void kernel_launch(void* const* d_in, const int* in_sizes, int n_in,
                              void* d_out, int out_size) {
    const float* x     = (const float*)d_in[0];
    const int*   ei    = (const int*)  d_in[1];
    const float* gatW0 = (const float*)d_in[2];
    const float* asrc0 = (const float*)d_in[3];
    const float* adst0 = (const float*)d_in[4];
    const float* gatb0 = (const float*)d_in[5];
    const float* fcW0  = (const float*)d_in[6];
    const float* fcb0  = (const float*)d_in[7];
    const float* shW0  = (const float*)d_in[8];
    const float* shb0  = (const float*)d_in[9];
    const float* scW0  = (const float*)d_in[10];
    const float* scb0  = (const float*)d_in[11];
    const float* gatW1 = (const float*)d_in[12];
    const float* asrc1 = (const float*)d_in[13];
    const float* adst1 = (const float*)d_in[14];
    const float* gatb1 = (const float*)d_in[15];
    const float* fcW1  = (const float*)d_in[16];
    const float* fcb1  = (const float*)d_in[17];
    const float* shW1  = (const float*)d_in[18];
    const float* shb1  = (const float*)d_in[19];
    const float* scW1  = (const float*)d_in[20];
    const float* scb1  = (const float*)d_in[21];
    const float* eps0  = (const float*)d_in[22];
    const float* eps1  = (const float*)d_in[23];

    const int n = N_NODES;
    float* out = (float*)d_out;
    float* theta0 = out;
    float* theta1 = theta0 + (size_t)128 * n;
    float* k0     = theta1 + (size_t)64  * n;
    float* k1     = k0     + (size_t)128 * n;
    float* l0     = k1     + (size_t)64  * n;
    float* l1     = l0     + (size_t)128 * n;

    float* xw0 = symaddrf(g_xw0);
    float* h0  = symaddrf(g_h0);
    float* xw1 = symaddrf(g_xw1);
    float* h1  = symaddrf(g_h1);
    float* z0  = symaddrf(g_z0);
    float* z1  = symaddrf(g_z1);
    float* s   = symaddrf(g_s);
    float* d   = symaddrf(g_d);
    int* cnt = symaddri(g_cnt);
    int* cur = symaddri(g_cur);
    int* off = symaddri(g_off);
    int* csr = symaddri(g_csr);

    const int EB = (ET + 255) / 256;
    const int GX = (n + 127) / 128;       // 157 row tiles
    dim3 blk128(16, 16);                  // BN=128 variant: 256 threads
    dim3 blk64(8, 16);                    // BN=64 variant: 128 threads

    // ---- CSR build + first GEMM (gemm xw0 placed at launch index 3 for ncu) ----
    zero_cnt_kernel<<<(n + 255) / 256, 256>>>(cnt);                                   // 0
    hist_kernel<<<EB, 256>>>(ei, cnt);                                                // 1
    scan_kernel<<<1, 1024>>>(cnt, off, cur);                                          // 2
    gemm2_kernel<128,128,16,8,8><<<dim3(GX,2), blk128>>>(x, gatW0, nullptr, xw0,
                                                          n, 256, 256, 0);            // 3 (profiled)
    scatter_kernel<<<EB, 256>>>(ei, off, cur, csr);                                   // 4

    // ---- layer 0 ----
    sd_kernel<<<(N_NODES * HEADS * 32 + 255) / 256, 256>>>(xw0, asrc0, adst0, s, d, 64);
    gat_kernel<64><<<n, 256>>>(csr, off, s, d, xw0, gatb0, h0);

    // ---- layer 1 inputs + z0 ----
    gemm2_kernel<128,128,16,8,8><<<dim3(GX,1), blk128>>>(h0, gatW1, nullptr, xw1, n, 256, 128, 0);
    gemm2_kernel<128,128,16,8,8><<<dim3(GX,1), blk128>>>(h0, fcW0, fcb0, z0, n, 256, 128, 1);

    // ---- layer 1 ----
    sd_kernel<<<(N_NODES * HEADS * 32 + 255) / 256, 256>>>(xw1, asrc1, adst1, s, d, 32);
    gat_kernel<32><<<n, 128>>>(csr, off, s, d, xw1, gatb1, h1);

    gemm2_kernel<128,64,16,8,8><<<dim3(GX,1), blk64>>>(h1, fcW1, fcb1, z1, n, 128, 64, 1);

    // ---- k / l heads ----
    gemm2_kernel<128,128,16,8,8><<<dim3(GX,1), blk128>>>(z0, shW0, shb0, k0, n, 128, 128, 2);
    gemm2_kernel<128,128,16,8,8><<<dim3(GX,1), blk128>>>(z0, scW0, scb0, l0, n, 128, 128, 3);
    gemm2_kernel<128,64,16,8,8><<<dim3(GX,1), blk64>>>(z1, shW1, shb1, k1, n, 64, 64, 2);
    gemm2_kernel<128,64,16,8,8><<<dim3(GX,1), blk64>>>(z1, scW1, scb1, l1, n, 64, 64, 3);

    // ---- fused kl_fix + theta ----
    theta_kernel<<<(128 * n + 255) / 256, 256>>>(k0, l0, eps0, theta0, 128 * n);
    theta_kernel<<<(64  * n + 255) / 256, 256>>>(k1, l1, eps1, theta1, 64 * n);
}

// round 5
// speedup vs baseline: 1.0099x; 1.0099x over previous
#include <cuda_runtime.h>
#include <math.h>

#define N_NODES 20000
#define NE      320000
#define ET      (NE + N_NODES)
#define HEADS   4

// ---------------- scratch (device globals; no allocation) ----------------
static __device__ float g_xw0[(size_t)N_NODES * 256];
static __device__ float g_h0 [(size_t)N_NODES * 256];
static __device__ float g_xw1[(size_t)N_NODES * 128];
static __device__ float g_h1 [(size_t)N_NODES * 128];
static __device__ float g_z0 [(size_t)N_NODES * 128];
static __device__ float g_z1 [(size_t)N_NODES * 64];
static __device__ float g_s  [N_NODES * 4];
static __device__ float g_d  [N_NODES * 4];
static __device__ int   g_cnt[N_NODES];
static __device__ int   g_cur[N_NODES];
static __device__ int   g_off[N_NODES + 1];
static __device__ int   g_csr[ET];
static __device__ float g_wf01[256 * 256];   // [gatW1 ; fcW0]
static __device__ float g_wkl0[256 * 128];   // [shW0 ; scW0]
static __device__ float g_wkl1[128 * 64];    // [shW1 ; scW1]

// ---------------- helpers ----------------
__device__ __forceinline__ float softplusf(float x) {
    return x > 20.f ? x : log1pf(__expf(x));
}
__device__ __forceinline__ float u64lo(unsigned long long u) {
    return __uint_as_float((unsigned)(u & 0xffffffffu));
}
__device__ __forceinline__ float u64hi(unsigned long long u) {
    return __uint_as_float((unsigned)(u >> 32));
}
__device__ __forceinline__ void edge_uv(const int* __restrict__ ei, int e, int& u, int& v) {
    if (e < NE) { u = ei[e]; v = ei[NE + e]; }
    else        { u = v = e - NE; }   // self loops appended
}

// ---------------- simple device copy (graph-safe weight concat) ----------------
__global__ void copy_kernel(float* __restrict__ dst, const float* __restrict__ src, int count) {
    int i = blockIdx.x * blockDim.x + threadIdx.x;
    if (i < count) dst[i] = src[i];
}

// ================= CSR build (group edges by dst) =================
__global__ void zero_cnt_kernel(int* __restrict__ cnt) {
    int i = blockIdx.x * blockDim.x + threadIdx.x;
    if (i < N_NODES) cnt[i] = 0;
}

__global__ void hist_kernel(const int* __restrict__ ei, int* __restrict__ cnt) {
    int e = blockIdx.x * blockDim.x + threadIdx.x;
    if (e >= ET) return;
    int u, v; edge_uv(ei, e, u, v);
    (void)u;
    atomicAdd(&cnt[v], 1);
}

__global__ void scan_kernel(const int* __restrict__ cnt, int* __restrict__ off,
                            int* __restrict__ cur) {
    const int CHUNK = (N_NODES + 1023) / 1024;   // 20
    __shared__ int ts[1024];
    int tid = threadIdx.x;
    int base = tid * CHUNK;
    int s = 0;
    for (int i = 0; i < CHUNK; i++) {
        int idx = base + i;
        if (idx < N_NODES) s += cnt[idx];
    }
    ts[tid] = s;
    __syncthreads();
    for (int o = 1; o < 1024; o <<= 1) {
        int v = (tid >= o) ? ts[tid - o] : 0;
        __syncthreads();
        ts[tid] += v;
        __syncthreads();
    }
    int run = (tid > 0) ? ts[tid - 1] : 0;
    for (int i = 0; i < CHUNK; i++) {
        int idx = base + i;
        if (idx < N_NODES) {
            off[idx] = run;
            run += cnt[idx];
            cur[idx] = 0;
        }
    }
    if (tid == (N_NODES - 1) / CHUNK) off[N_NODES] = run;
}

__global__ void scatter_kernel(const int* __restrict__ ei, const int* __restrict__ off,
                               int* __restrict__ cur, int* __restrict__ csr) {
    int e = blockIdx.x * blockDim.x + threadIdx.x;
    if (e >= ET) return;
    int u, v; edge_uv(ei, e, u, v);
    int pos = off[v] + atomicAdd(&cur[v], 1);
    csr[pos] = u;
}

// ================= f32x2 GEMM v2: BM=64, double-buffered, dual-segment epilogue =====
// C = A[n,K] * W[Ntot,K]^T, output split at nsplit into (outA, outB).
// mode: 0 plain rowmajor, 1 softplus rowmajor, 2 softplus+clip transposed, 3 softplus transposed
template<int BN, int TN>
__global__ void __launch_bounds__(256)
gemm2_kernel(const float* __restrict__ A, const float* __restrict__ W,
             int n, int K, int nsplit,
             float* __restrict__ outA, const float* __restrict__ biasA, int modeA, int strideA,
             float* __restrict__ outB, const float* __restrict__ biasB, int modeB, int strideB) {
    constexpr int BM = 64, BK = 16, TM = 4;
    constexpr int BX = BN / TN;          // 16
    constexpr int BY = BM / TM;          // 16
    constexpr int KQ = BK / 4;           // 4
    constexpr int ASTR = BM + 4;         // 68 floats
    constexpr int BSTR = BN + 1;         // float2 units
    constexpr int BF = BN / 64;          // B float4 loads per thread per stage (1 or 2)

    __shared__ __align__(16) float  Ast[2][BK * ASTR];
    __shared__ __align__(16) float2 Bsd[2][BK * BSTR];

    const int bi = blockIdx.x * BM;
    const int bj = blockIdx.y * BN;
    const int tx = threadIdx.x, ty = threadIdx.y;
    const int t = ty * BX + tx;          // 0..255

    // global load indices (fixed per thread)
    const int arow = t >> 2;             // 0..63
    const int akq  = t & 3;
    const bool avalid = (bi + arow) < n;
    const float* aptr = A + (size_t)(bi + arow) * K + akq * 4;

    unsigned long long acc[TM / 2][TN];
#pragma unroll
    for (int r = 0; r < TM / 2; r++)
#pragma unroll
        for (int c = 0; c < TN; c++) acc[r][c] = 0ull;

    const int KT = K / BK;

    // prologue: load stage 0
    {
        float4 av = make_float4(0.f, 0.f, 0.f, 0.f);
        if (avalid) av = *(const float4*)(aptr);
        Ast[0][(4 * akq + 0) * ASTR + arow] = av.x;
        Ast[0][(4 * akq + 1) * ASTR + arow] = av.y;
        Ast[0][(4 * akq + 2) * ASTR + arow] = av.z;
        Ast[0][(4 * akq + 3) * ASTR + arow] = av.w;
#pragma unroll
        for (int q = 0; q < BF; q++) {
            int idx = t + q * 256;
            int col = idx / KQ, kq = idx % KQ;
            float4 bv = *(const float4*)(W + (size_t)(bj + col) * K + kq * 4);
            Bsd[0][(4 * kq + 0) * BSTR + col] = make_float2(bv.x, bv.x);
            Bsd[0][(4 * kq + 1) * BSTR + col] = make_float2(bv.y, bv.y);
            Bsd[0][(4 * kq + 2) * BSTR + col] = make_float2(bv.z, bv.z);
            Bsd[0][(4 * kq + 3) * BSTR + col] = make_float2(bv.w, bv.w);
        }
    }
    __syncthreads();

    for (int kt = 0; kt < KT; kt++) {
        const int cur = kt & 1;
        float4 apre = make_float4(0.f, 0.f, 0.f, 0.f);
        float4 bpre[BF];
        if (kt + 1 < KT) {
            int k0 = (kt + 1) * BK;
            if (avalid) apre = *(const float4*)(aptr + k0);
#pragma unroll
            for (int q = 0; q < BF; q++) {
                int idx = t + q * 256;
                int col = idx / KQ, kq = idx % KQ;
                bpre[q] = *(const float4*)(W + (size_t)(bj + col) * K + k0 + kq * 4);
            }
        }

#pragma unroll
        for (int kk = 0; kk < BK; kk++) {
            ulonglong2 a2 = *(const ulonglong2*)&Ast[cur][kk * ASTR + ty * TM];
            unsigned long long av[2] = {a2.x, a2.y};
            unsigned long long bv[TN];
#pragma unroll
            for (int c = 0; c < TN; c++)
                bv[c] = *(const unsigned long long*)&Bsd[cur][kk * BSTR + tx + BX * c];
#pragma unroll
            for (int r = 0; r < TM / 2; r++)
#pragma unroll
                for (int c = 0; c < TN; c++)
                    asm("fma.rn.f32x2 %0, %1, %2, %0;"
                        : "+l"(acc[r][c]) : "l"(av[r]), "l"(bv[c]));
        }

        if (kt + 1 < KT) {
            const int nxt = cur ^ 1;
            Ast[nxt][(4 * akq + 0) * ASTR + arow] = apre.x;
            Ast[nxt][(4 * akq + 1) * ASTR + arow] = apre.y;
            Ast[nxt][(4 * akq + 2) * ASTR + arow] = apre.z;
            Ast[nxt][(4 * akq + 3) * ASTR + arow] = apre.w;
#pragma unroll
            for (int q = 0; q < BF; q++) {
                int idx = t + q * 256;
                int col = idx / KQ, kq = idx % KQ;
                Bsd[nxt][(4 * kq + 0) * BSTR + col] = make_float2(bpre[q].x, bpre[q].x);
                Bsd[nxt][(4 * kq + 1) * BSTR + col] = make_float2(bpre[q].y, bpre[q].y);
                Bsd[nxt][(4 * kq + 2) * BSTR + col] = make_float2(bpre[q].z, bpre[q].z);
                Bsd[nxt][(4 * kq + 3) * BSTR + col] = make_float2(bpre[q].w, bpre[q].w);
            }
        }
        __syncthreads();
    }

    // ---- epilogue (dual segment) ----
#pragma unroll
    for (int r = 0; r < TM / 2; r++) {
        int i0 = bi + ty * TM + 2 * r;
#pragma unroll
        for (int c = 0; c < TN; c++) {
            int jj = bj + tx + BX * c;
            float* out; const float* bias; int mode, stride, j;
            if (jj < nsplit) { out = outA; bias = biasA; mode = modeA; stride = strideA; j = jj; }
            else             { out = outB; bias = biasB; mode = modeB; stride = strideB; j = jj - nsplit; }
            float v0 = u64lo(acc[r][c]);
            float v1 = u64hi(acc[r][c]);
            float b = bias ? bias[j] : 0.f;
            v0 += b; v1 += b;
            if (mode != 0) { v0 = softplusf(v0); v1 = softplusf(v1); }
            if (mode == 2) {
                v0 = fminf(fmaxf(v0, 0.1f), 1000.f);
                v1 = fminf(fmaxf(v1, 0.1f), 1000.f);
            }
            if (mode >= 2) {
                if (i0 + 1 < n) *(float2*)&out[(size_t)j * stride + i0] = make_float2(v0, v1);
                else if (i0 < n) out[(size_t)j * stride + i0] = v0;
            } else {
                if (i0 < n)     out[(size_t)i0 * stride + j] = v0;
                if (i0 + 1 < n) out[(size_t)(i0 + 1) * stride + j] = v1;
            }
        }
    }
}

// ---------------- attention source/dest scores: one warp per (node, head) ----------------
__global__ void sd_kernel(const float* __restrict__ xw,
                          const float* __restrict__ asrc, const float* __restrict__ adst,
                          float* __restrict__ s, float* __restrict__ d, int C) {
    int warp = (blockIdx.x * blockDim.x + threadIdx.x) >> 5;
    int lane = threadIdx.x & 31;
    if (warp >= N_NODES * HEADS) return;
    int node = warp >> 2, h = warp & 3;
    const float* base = xw + (size_t)node * HEADS * C + h * C;
    float ss = 0.f, dd = 0.f;
    for (int c = lane; c < C; c += 32) {
        float v = base[c];
        ss += v * asrc[h * C + c];
        dd += v * adst[h * C + c];
    }
#pragma unroll
    for (int o = 16; o; o >>= 1) {
        ss += __shfl_down_sync(0xffffffffu, ss, o);
        dd += __shfl_down_sync(0xffffffffu, dd, o);
    }
    if (lane == 0) { s[warp] = ss; d[warp] = dd; }
}

// ================= fused per-node GAT softmax + aggregation =================
template <int C>
__global__ void gat_kernel(const int* __restrict__ csr, const int* __restrict__ off,
                           const float* __restrict__ s, const float* __restrict__ d,
                           const float* __restrict__ xw, const float* __restrict__ bias,
                           float* __restrict__ out) {
    constexpr int HC = 4 * C;
    const int v = blockIdx.x;
    const int tid = threadIdx.x;
    const int h = tid / C;
    const int c = tid - h * C;           // in-head lane 0..C-1
    const int beg = off[v], end = off[v + 1];

    __shared__ float red[HC];
    __shared__ float mh[4], inv[4];

    const float dv = d[v * 4 + h];

    float lmax = -INFINITY;
    for (int j = beg + c; j < end; j += C) {
        int u = csr[j];
        float e = s[u * 4 + h] + dv;
        e = e > 0.f ? e : 0.2f * e;
        lmax = fmaxf(lmax, e);
    }
    red[tid] = lmax;
    __syncthreads();
    if (tid < 4) {
        float m = -INFINITY;
        for (int i = 0; i < C; i++) m = fmaxf(m, red[tid * C + i]);
        mh[tid] = m;
    }
    __syncthreads();
    const float m = mh[h];

    float lsum = 0.f;
    for (int j = beg + c; j < end; j += C) {
        int u = csr[j];
        float e = s[u * 4 + h] + dv;
        e = e > 0.f ? e : 0.2f * e;
        lsum += __expf(e - m);
    }
    red[tid] = lsum;
    __syncthreads();
    if (tid < 4) {
        float sm = 0.f;
        for (int i = 0; i < C; i++) sm += red[tid * C + i];
        inv[tid] = 1.f / (sm + 1e-16f);
    }
    __syncthreads();
    const float invden = inv[h];

    float acc = 0.f;
    for (int j = beg; j < end; j++) {
        int u = csr[j];
        float e = s[u * 4 + h] + dv;
        e = e > 0.f ? e : 0.2f * e;
        float w = __expf(e - m) * invden;
        acc = fmaf(w, xw[(size_t)u * HC + tid], acc);
    }
    out[(size_t)v * HC + tid] = acc + bias[tid];
}

// ---------------- fused kl_fix + theta ----------------
__global__ void theta_kernel(const float* __restrict__ k, float* __restrict__ l,
                             const float* __restrict__ eps, float* __restrict__ th, int ZN) {
    int i = blockIdx.x * blockDim.x + threadIdx.x;
    if (i >= ZN) return;
    float kk = k[i];
    float invk = 1.f / kk;
    float ll = fmaxf(l[i], 2.2e-10f) * expf(-lgammaf(1.f + invk));
    l[i] = ll;
    float acc = 0.f;
#pragma unroll
    for (int s = 0; s < 10; s++) {
        float ep = eps[(size_t)s * ZN + i];
        float t = fmaxf(1.f - ep, 2.2e-10f);
        float nl = -__logf(t);
        acc += __powf(nl, invk);
    }
    float theta = ll * acc * 0.1f;
    th[i] = fminf(fmaxf(theta, 2.2e-10f), 1000.f);
}

// ---------------- host launch ----------------
template <typename T>
static float* symaddrf(T& sym) { void* p = nullptr; cudaGetSymbolAddress(&p, sym); return (float*)p; }
template <typename T>
static int* symaddri(T& sym) { void* p = nullptr; cudaGetSymbolAddress(&p, sym); return (int*)p; }

extern "C" void kernel_launch(void* const* d_in, const int* in_sizes, int n_in,
                              void* d_out, int out_size) {
    const float* x     = (const float*)d_in[0];
    const int*   ei    = (const int*)  d_in[1];
    const float* gatW0 = (const float*)d_in[2];
    const float* asrc0 = (const float*)d_in[3];
    const float* adst0 = (const float*)d_in[4];
    const float* gatb0 = (const float*)d_in[5];
    const float* fcW0  = (const float*)d_in[6];
    const float* fcb0  = (const float*)d_in[7];
    const float* shW0  = (const float*)d_in[8];
    const float* shb0  = (const float*)d_in[9];
    const float* scW0  = (const float*)d_in[10];
    const float* scb0  = (const float*)d_in[11];
    const float* gatW1 = (const float*)d_in[12];
    const float* asrc1 = (const float*)d_in[13];
    const float* adst1 = (const float*)d_in[14];
    const float* gatb1 = (const float*)d_in[15];
    const float* fcW1  = (const float*)d_in[16];
    const float* fcb1  = (const float*)d_in[17];
    const float* shW1  = (const float*)d_in[18];
    const float* shb1  = (const float*)d_in[19];
    const float* scW1  = (const float*)d_in[20];
    const float* scb1  = (const float*)d_in[21];
    const float* eps0  = (const float*)d_in[22];
    const float* eps1  = (const float*)d_in[23];

    const int n = N_NODES;
    float* out = (float*)d_out;
    float* theta0 = out;
    float* theta1 = theta0 + (size_t)128 * n;
    float* k0     = theta1 + (size_t)64  * n;
    float* k1     = k0     + (size_t)128 * n;
    float* l0     = k1     + (size_t)64  * n;
    float* l1     = l0     + (size_t)128 * n;

    float* xw0 = symaddrf(g_xw0);
    float* h0  = symaddrf(g_h0);
    float* xw1 = symaddrf(g_xw1);
    float* h1  = symaddrf(g_h1);
    float* z0  = symaddrf(g_z0);
    float* z1  = symaddrf(g_z1);
    float* s   = symaddrf(g_s);
    float* d   = symaddrf(g_d);
    float* wf01 = symaddrf(g_wf01);
    float* wkl0 = symaddrf(g_wkl0);
    float* wkl1 = symaddrf(g_wkl1);
    int* cnt = symaddri(g_cnt);
    int* cur = symaddri(g_cur);
    int* off = symaddri(g_off);
    int* csr = symaddri(g_csr);

    const int EB = (ET + 255) / 256;
    const int GX = (n + 63) / 64;         // 313 row tiles
    dim3 blk(16, 16);

    // ---- CSR build; xw0 GEMM at launch index 3 (profiled) ----
    zero_cnt_kernel<<<(n + 255) / 256, 256>>>(cnt);                                   // 0
    hist_kernel<<<EB, 256>>>(ei, cnt);                                                // 1
    scan_kernel<<<1, 1024>>>(cnt, off, cur);                                          // 2
    gemm2_kernel<128, 8><<<dim3(GX, 2), blk>>>(x, gatW0, n, 256, 1 << 30,
                                               xw0, nullptr, 0, 256,
                                               nullptr, nullptr, 0, 0);                // 3 (profiled)
    scatter_kernel<<<EB, 256>>>(ei, off, cur, csr);                                   // 4

    // ---- weight concats (device copies; graph-safe) ----
    copy_kernel<<<128, 256>>>(wf01,          gatW1, 128 * 256);
    copy_kernel<<<128, 256>>>(wf01 + 32768,  fcW0,  128 * 256);
    copy_kernel<<<64,  256>>>(wkl0,          shW0,  128 * 128);
    copy_kernel<<<64,  256>>>(wkl0 + 16384,  scW0,  128 * 128);
    copy_kernel<<<16,  256>>>(wkl1,          shW1,  64 * 64);
    copy_kernel<<<16,  256>>>(wkl1 + 4096,   scW1,  64 * 64);

    // ---- layer 0 ----
    sd_kernel<<<(N_NODES * HEADS * 32 + 255) / 256, 256>>>(xw0, asrc0, adst0, s, d, 64);
    gat_kernel<64><<<n, 256>>>(csr, off, s, d, xw0, gatb0, h0);

    // ---- fused xw1 + z0 (both consume h0, K=256) ----
    gemm2_kernel<128, 8><<<dim3(GX, 2), blk>>>(h0, wf01, n, 256, 128,
                                               xw1, nullptr, 0, 128,
                                               z0, fcb0, 1, 128);

    // ---- layer 1 ----
    sd_kernel<<<(N_NODES * HEADS * 32 + 255) / 256, 256>>>(xw1, asrc1, adst1, s, d, 32);
    gat_kernel<32><<<n, 128>>>(csr, off, s, d, xw1, gatb1, h1);

    // ---- z1 (K=128, N=64) ----
    gemm2_kernel<64, 4><<<dim3(GX, 1), blk>>>(h1, fcW1, n, 128, 1 << 30,
                                              z1, fcb1, 1, 64,
                                              nullptr, nullptr, 0, 0);

    // ---- fused k0 + l0 (both consume z0, K=128, transposed stores) ----
    gemm2_kernel<128, 8><<<dim3(GX, 2), blk>>>(z0, wkl0, n, 128, 128,
                                               k0, shb0, 2, n,
                                               l0, scb0, 3, n);

    // ---- fused k1 + l1 (both consume z1, K=64, transposed stores) ----
    gemm2_kernel<128, 8><<<dim3(GX, 1), blk>>>(z1, wkl1, n, 64, 64,
                                               k1, shb1, 2, n,
                                               l1, scb1, 3, n);

    // ---- fused kl_fix + theta ----
    theta_kernel<<<(128 * n + 255) / 256, 256>>>(k0, l0, eps0, theta0, 128 * n);
    theta_kernel<<<(64  * n + 255) / 256, 256>>>(k1, l1, eps1, theta1, 64 * n);
}

// round 7
// speedup vs baseline: 1.0263x; 1.0162x over previous
#include <cuda_runtime.h>
#include <math.h>
#include <stdint.h>

#define N_NODES 20000
#define NE      320000
#define ET      (NE + N_NODES)
#define HEADS   4

// ---------------- scratch (device globals; no allocation) ----------------
static __device__ float g_xw0[(size_t)N_NODES * 256];
static __device__ float g_h0 [(size_t)N_NODES * 256];
static __device__ float g_xw1[(size_t)N_NODES * 128];
static __device__ float g_h1 [(size_t)N_NODES * 128];
static __device__ float g_z0 [(size_t)N_NODES * 128];
static __device__ float g_z1 [(size_t)N_NODES * 64];
static __device__ float g_s  [N_NODES * 4];
static __device__ float g_d  [N_NODES * 4];
static __device__ int   g_cnt[N_NODES];
static __device__ int   g_cur[N_NODES];
static __device__ int   g_off[N_NODES + 1];
static __device__ int   g_csr[ET];
static __device__ float g_wf01[256 * 256];   // [gatW1 ; fcW0]
static __device__ float g_wkl0[256 * 128];   // [shW0 ; scW0]
static __device__ float g_wkl1[128 * 64];    // [shW1 ; scW1]

// ---------------- helpers ----------------
__device__ __forceinline__ float softplusf(float x) {
    return x > 20.f ? x : log1pf(__expf(x));
}
__device__ __forceinline__ void edge_uv(const int* __restrict__ ei, int e, int& u, int& v) {
    if (e < NE) { u = ei[e]; v = ei[NE + e]; }
    else        { u = v = e - NE; }   // self loops appended
}
__device__ __forceinline__ float tf32_round(float x) {
    uint32_t u;
    asm("cvt.rna.tf32.f32 %0, %1;" : "=r"(u) : "f"(x));
    return __uint_as_float(u);
}
__device__ __forceinline__ void split4(float4 v, float4& h, float4& l) {
    h.x = tf32_round(v.x); l.x = tf32_round(v.x - h.x);
    h.y = tf32_round(v.y); l.y = tf32_round(v.y - h.y);
    h.z = tf32_round(v.z); l.z = tf32_round(v.z - h.z);
    h.w = tf32_round(v.w); l.w = tf32_round(v.w - h.w);
}
__device__ __forceinline__ void mma8(float* c, const float* a, const float* b) {
    asm volatile(
        "mma.sync.aligned.m16n8k8.row.col.f32.tf32.tf32.f32 "
        "{%0,%1,%2,%3}, {%4,%5,%6,%7}, {%8,%9}, {%0,%1,%2,%3};"
        : "+f"(c[0]), "+f"(c[1]), "+f"(c[2]), "+f"(c[3])
        : "r"(__float_as_uint(a[0])), "r"(__float_as_uint(a[1])),
          "r"(__float_as_uint(a[2])), "r"(__float_as_uint(a[3])),
          "r"(__float_as_uint(b[0])), "r"(__float_as_uint(b[1])));
}

// ---------------- simple device copy (graph-safe weight concat) ----------------
__global__ void copy_kernel(float* __restrict__ dst, const float* __restrict__ src, int count) {
    int i = blockIdx.x * blockDim.x + threadIdx.x;
    if (i < count) dst[i] = src[i];
}

// ================= CSR build (group edges by dst) =================
__global__ void zero_cnt_kernel(int* __restrict__ cnt) {
    int i = blockIdx.x * blockDim.x + threadIdx.x;
    if (i < N_NODES) cnt[i] = 0;
}

__global__ void hist_kernel(const int* __restrict__ ei, int* __restrict__ cnt) {
    int e = blockIdx.x * blockDim.x + threadIdx.x;
    if (e >= ET) return;
    int u, v; edge_uv(ei, e, u, v);
    (void)u;
    atomicAdd(&cnt[v], 1);
}

__global__ void scan_kernel(const int* __restrict__ cnt, int* __restrict__ off,
                            int* __restrict__ cur) {
    const int CHUNK = (N_NODES + 1023) / 1024;   // 20
    __shared__ int ts[1024];
    int tid = threadIdx.x;
    int base = tid * CHUNK;
    int s = 0;
    for (int i = 0; i < CHUNK; i++) {
        int idx = base + i;
        if (idx < N_NODES) s += cnt[idx];
    }
    ts[tid] = s;
    __syncthreads();
    for (int o = 1; o < 1024; o <<= 1) {
        int v = (tid >= o) ? ts[tid - o] : 0;
        __syncthreads();
        ts[tid] += v;
        __syncthreads();
    }
    int run = (tid > 0) ? ts[tid - 1] : 0;
    for (int i = 0; i < CHUNK; i++) {
        int idx = base + i;
        if (idx < N_NODES) {
            off[idx] = run;
            run += cnt[idx];
            cur[idx] = 0;
        }
    }
    if (tid == (N_NODES - 1) / CHUNK) off[N_NODES] = run;
}

__global__ void scatter_kernel(const int* __restrict__ ei, const int* __restrict__ off,
                               int* __restrict__ cur, int* __restrict__ csr) {
    int e = blockIdx.x * blockDim.x + threadIdx.x;
    if (e >= ET) return;
    int u, v; edge_uv(ei, e, u, v);
    int pos = off[v] + atomicAdd(&cur[v], 1);
    csr[pos] = u;
}

// ================= 3xTF32 mma.sync GEMM =================
// C[n, Ntot] = A[n,K] * W[Ntot,K]^T; CTA tile 128 x BN, 8 warps (4 along M, 2 along N).
// Split-tf32: D = Ahi*Bhi + Ahi*Blo + Alo*Bhi (fp32 accumulate) ~ fp32 accuracy.
// Output split at nsplit; mode: 0 plain rowmajor, 1 softplus rowmajor,
//                              2 softplus+clip transposed, 3 softplus transposed.
template<int BN>
__global__ void __launch_bounds__(256)
gemm_mma_kernel(const float* __restrict__ A, const float* __restrict__ W,
                int n, int K, int nsplit,
                float* __restrict__ outA, const float* __restrict__ biasA, int modeA, int strideA,
                float* __restrict__ outB, const float* __restrict__ biasB, int modeB, int strideB) {
    constexpr int BM = 128, BK = 16;
    constexpr int KP = 20;                     // padded row stride (floats), float4-aligned
    constexpr int NT = BN / 16;                // n-tiles (8 cols each) per warp
    constexpr int AF4 = BM * BK / 4 / 256;     // A float4 loads per thread (2)
    constexpr int BF4 = BN * BK / 4 / 256;     // B float4 loads per thread (2 or 1)

    __shared__ __align__(16) float Ah[BM * KP], Al[BM * KP];
    __shared__ __align__(16) float Bh[BN * KP], Bl[BN * KP];

    const int tid = threadIdx.x;
    const int wid = tid >> 5, lane = tid & 31;
    const int gr = lane >> 2, tig = lane & 3;
    const int warpM = (wid & 3) * 32;
    const int warpN = (wid >> 2) * (BN / 2);
    const int bi = blockIdx.x * BM;
    const int bj = blockIdx.y * BN;

    float acc[2][NT][4];
#pragma unroll
    for (int mt = 0; mt < 2; mt++)
#pragma unroll
        for (int nt = 0; nt < NT; nt++)
#pragma unroll
            for (int q = 0; q < 4; q++) acc[mt][nt][q] = 0.f;

    const int nchunk = K / BK;

    // per-thread global load slots
    int arows[AF4], aqs[AF4]; bool avs[AF4];
#pragma unroll
    for (int i = 0; i < AF4; i++) {
        int idx = tid + i * 256;
        arows[i] = idx >> 2; aqs[i] = idx & 3;
        avs[i] = (bi + arows[i]) < n;
    }
    int brows[BF4], bqs[BF4];
#pragma unroll
    for (int i = 0; i < BF4; i++) {
        int idx = tid + i * 256;
        brows[i] = idx >> 2; bqs[i] = idx & 3;
    }

    float4 apre[AF4], bpre[BF4];
#pragma unroll
    for (int i = 0; i < AF4; i++)
        apre[i] = avs[i] ? *(const float4*)(A + (size_t)(bi + arows[i]) * K + aqs[i] * 4)
                         : make_float4(0.f, 0.f, 0.f, 0.f);
#pragma unroll
    for (int i = 0; i < BF4; i++)
        bpre[i] = *(const float4*)(W + (size_t)(bj + brows[i]) * K + bqs[i] * 4);

    for (int c = 0; c < nchunk; c++) {
        // store current chunk (split hi/lo)
#pragma unroll
        for (int i = 0; i < AF4; i++) {
            float4 h, l; split4(apre[i], h, l);
            *(float4*)&Ah[arows[i] * KP + aqs[i] * 4] = h;
            *(float4*)&Al[arows[i] * KP + aqs[i] * 4] = l;
        }
#pragma unroll
        for (int i = 0; i < BF4; i++) {
            float4 h, l; split4(bpre[i], h, l);
            *(float4*)&Bh[brows[i] * KP + bqs[i] * 4] = h;
            *(float4*)&Bl[brows[i] * KP + bqs[i] * 4] = l;
        }
        __syncthreads();

        // prefetch next chunk
        if (c + 1 < nchunk) {
            int k0 = (c + 1) * BK;
#pragma unroll
            for (int i = 0; i < AF4; i++)
                apre[i] = avs[i] ? *(const float4*)(A + (size_t)(bi + arows[i]) * K + k0 + aqs[i] * 4)
                                 : make_float4(0.f, 0.f, 0.f, 0.f);
#pragma unroll
            for (int i = 0; i < BF4; i++)
                bpre[i] = *(const float4*)(W + (size_t)(bj + brows[i]) * K + k0 + bqs[i] * 4);
        }

        // compute: 2 k8 steps
#pragma unroll
        for (int kb = 0; kb < BK; kb += 8) {
            float ah[2][4], al[2][4];
#pragma unroll
            for (int mt = 0; mt < 2; mt++) {
                int r0 = (warpM + mt * 16 + gr) * KP + kb + tig;
                int r1 = (warpM + mt * 16 + gr + 8) * KP + kb + tig;
                ah[mt][0] = Ah[r0];     ah[mt][1] = Ah[r1];
                ah[mt][2] = Ah[r0 + 4]; ah[mt][3] = Ah[r1 + 4];
                al[mt][0] = Al[r0];     al[mt][1] = Al[r1];
                al[mt][2] = Al[r0 + 4]; al[mt][3] = Al[r1 + 4];
            }
#pragma unroll
            for (int nt = 0; nt < NT; nt++) {
                int b0 = (warpN + nt * 8 + gr) * KP + kb + tig;
                float bh[2] = {Bh[b0], Bh[b0 + 4]};
                float bl[2] = {Bl[b0], Bl[b0 + 4]};
#pragma unroll
                for (int mt = 0; mt < 2; mt++) {
                    mma8(acc[mt][nt], ah[mt], bh);
                    mma8(acc[mt][nt], ah[mt], bl);
                    mma8(acc[mt][nt], al[mt], bh);
                }
            }
        }
        __syncthreads();
    }

    // ---- epilogue ----
#pragma unroll
    for (int mt = 0; mt < 2; mt++) {
#pragma unroll
        for (int nt = 0; nt < NT; nt++) {
#pragma unroll
            for (int half = 0; half < 2; half++) {       // c0/c1 then c2/c3
                int row = bi + warpM + mt * 16 + gr + half * 8;
                if (row >= n) continue;
#pragma unroll
                for (int p = 0; p < 2; p++) {
                    int jj = bj + warpN + nt * 8 + 2 * tig + p;
                    float v = acc[mt][nt][half * 2 + p];
                    float* o; const float* bp; int mode, stride, j;
                    if (jj < nsplit) { o = outA; bp = biasA; mode = modeA; stride = strideA; j = jj; }
                    else             { o = outB; bp = biasB; mode = modeB; stride = strideB; j = jj - nsplit; }
                    v += bp ? bp[j] : 0.f;
                    if (mode != 0) v = softplusf(v);
                    if (mode == 2) v = fminf(fmaxf(v, 0.1f), 1000.f);
                    if (mode >= 2) o[(size_t)j * stride + row] = v;
                    else           o[(size_t)row * stride + j] = v;
                }
            }
        }
    }
}

// ---------------- attention source/dest scores: one warp per (node, head) ----------------
__global__ void sd_kernel(const float* __restrict__ xw,
                          const float* __restrict__ asrc, const float* __restrict__ adst,
                          float* __restrict__ s, float* __restrict__ d, int C) {
    int warp = (blockIdx.x * blockDim.x + threadIdx.x) >> 5;
    int lane = threadIdx.x & 31;
    if (warp >= N_NODES * HEADS) return;
    int node = warp >> 2, h = warp & 3;
    const float* base = xw + (size_t)node * HEADS * C + h * C;
    float ss = 0.f, dd = 0.f;
    for (int c = lane; c < C; c += 32) {
        float v = base[c];
        ss += v * asrc[h * C + c];
        dd += v * adst[h * C + c];
    }
#pragma unroll
    for (int o = 16; o; o >>= 1) {
        ss += __shfl_down_sync(0xffffffffu, ss, o);
        dd += __shfl_down_sync(0xffffffffu, dd, o);
    }
    if (lane == 0) { s[warp] = ss; d[warp] = dd; }
}

// ================= fused per-node GAT softmax + aggregation =================
template <int C>
__global__ void gat_kernel(const int* __restrict__ csr, const int* __restrict__ off,
                           const float* __restrict__ s, const float* __restrict__ d,
                           const float* __restrict__ xw, const float* __restrict__ bias,
                           float* __restrict__ out) {
    constexpr int HC = 4 * C;
    const int v = blockIdx.x;
    const int tid = threadIdx.x;
    const int h = tid / C;
    const int c = tid - h * C;           // in-head lane 0..C-1
    const int beg = off[v], end = off[v + 1];

    __shared__ float red[HC];
    __shared__ float mh[4], inv[4];

    const float dv = d[v * 4 + h];

    float lmax = -INFINITY;
    for (int j = beg + c; j < end; j += C) {
        int u = csr[j];
        float e = s[u * 4 + h] + dv;
        e = e > 0.f ? e : 0.2f * e;
        lmax = fmaxf(lmax, e);
    }
    red[tid] = lmax;
    __syncthreads();
    if (tid < 4) {
        float m = -INFINITY;
        for (int i = 0; i < C; i++) m = fmaxf(m, red[tid * C + i]);
        mh[tid] = m;
    }
    __syncthreads();
    const float m = mh[h];

    float lsum = 0.f;
    for (int j = beg + c; j < end; j += C) {
        int u = csr[j];
        float e = s[u * 4 + h] + dv;
        e = e > 0.f ? e : 0.2f * e;
        lsum += __expf(e - m);
    }
    red[tid] = lsum;
    __syncthreads();
    if (tid < 4) {
        float sm = 0.f;
        for (int i = 0; i < C; i++) sm += red[tid * C + i];
        inv[tid] = 1.f / (sm + 1e-16f);
    }
    __syncthreads();
    const float invden = inv[h];

    float acc = 0.f;
    for (int j = beg; j < end; j++) {
        int u = csr[j];
        float e = s[u * 4 + h] + dv;
        e = e > 0.f ? e : 0.2f * e;
        float w = __expf(e - m) * invden;
        acc = fmaf(w, xw[(size_t)u * HC + tid], acc);
    }
    out[(size_t)v * HC + tid] = acc + bias[tid];
}

// ---------------- fused kl_fix + theta ----------------
__global__ void theta_kernel(const float* __restrict__ k, float* __restrict__ l,
                             const float* __restrict__ eps, float* __restrict__ th, int ZN) {
    int i = blockIdx.x * blockDim.x + threadIdx.x;
    if (i >= ZN) return;
    float kk = k[i];
    float invk = 1.f / kk;
    float ll = fmaxf(l[i], 2.2e-10f) * expf(-lgammaf(1.f + invk));
    l[i] = ll;
    float acc = 0.f;
#pragma unroll
    for (int s = 0; s < 10; s++) {
        float ep = eps[(size_t)s * ZN + i];
        float t = fmaxf(1.f - ep, 2.2e-10f);
        float nl = -__logf(t);
        acc += __powf(nl, invk);
    }
    float theta = ll * acc * 0.1f;
    th[i] = fminf(fmaxf(theta, 2.2e-10f), 1000.f);
}

// ---------------- host launch ----------------
template <typename T>
static float* symaddrf(T& sym) { void* p = nullptr; cudaGetSymbolAddress(&p, sym); return (float*)p; }
template <typename T>
static int* symaddri(T& sym) { void* p = nullptr; cudaGetSymbolAddress(&p, sym); return (int*)p; }

extern "C" void kernel_launch(void* const* d_in, const int* in_sizes, int n_in,
                              void* d_out, int out_size) {
    const float* x     = (const float*)d_in[0];
    const int*   ei    = (const int*)  d_in[1];
    const float* gatW0 = (const float*)d_in[2];
    const float* asrc0 = (const float*)d_in[3];
    const float* adst0 = (const float*)d_in[4];
    const float* gatb0 = (const float*)d_in[5];
    const float* fcW0  = (const float*)d_in[6];
    const float* fcb0  = (const float*)d_in[7];
    const float* shW0  = (const float*)d_in[8];
    const float* shb0  = (const float*)d_in[9];
    const float* scW0  = (const float*)d_in[10];
    const float* scb0  = (const float*)d_in[11];
    const float* gatW1 = (const float*)d_in[12];
    const float* asrc1 = (const float*)d_in[13];
    const float* adst1 = (const float*)d_in[14];
    const float* gatb1 = (const float*)d_in[15];
    const float* fcW1  = (const float*)d_in[16];
    const float* fcb1  = (const float*)d_in[17];
    const float* shW1  = (const float*)d_in[18];
    const float* shb1  = (const float*)d_in[19];
    const float* scW1  = (const float*)d_in[20];
    const float* scb1  = (const float*)d_in[21];
    const float* eps0  = (const float*)d_in[22];
    const float* eps1  = (const float*)d_in[23];

    const int n = N_NODES;
    float* out = (float*)d_out;
    float* theta0 = out;
    float* theta1 = theta0 + (size_t)128 * n;
    float* k0     = theta1 + (size_t)64  * n;
    float* k1     = k0     + (size_t)128 * n;
    float* l0     = k1     + (size_t)64  * n;
    float* l1     = l0     + (size_t)128 * n;

    float* xw0 = symaddrf(g_xw0);
    float* h0  = symaddrf(g_h0);
    float* xw1 = symaddrf(g_xw1);
    float* h1  = symaddrf(g_h1);
    float* z0  = symaddrf(g_z0);
    float* z1  = symaddrf(g_z1);
    float* s   = symaddrf(g_s);
    float* d   = symaddrf(g_d);
    float* wf01 = symaddrf(g_wf01);
    float* wkl0 = symaddrf(g_wkl0);
    float* wkl1 = symaddrf(g_wkl1);
    int* cnt = symaddri(g_cnt);
    int* cur = symaddri(g_cur);
    int* off = symaddri(g_off);
    int* csr = symaddri(g_csr);

    const int EB = (ET + 255) / 256;
    const int GX = (n + 127) / 128;       // 157 row tiles

    // ---- CSR build; xw0 GEMM at launch index 3 (profiled) ----
    zero_cnt_kernel<<<(n + 255) / 256, 256>>>(cnt);                                   // 0
    hist_kernel<<<EB, 256>>>(ei, cnt);                                                // 1
    scan_kernel<<<1, 1024>>>(cnt, off, cur);                                          // 2
    gemm_mma_kernel<128><<<dim3(GX, 2), 256>>>(x, gatW0, n, 256, 1 << 30,
                                               xw0, nullptr, 0, 256,
                                               nullptr, nullptr, 0, 0);                // 3 (profiled)
    scatter_kernel<<<EB, 256>>>(ei, off, cur, csr);                                   // 4

    // ---- weight concats (device copies; graph-safe) ----
    copy_kernel<<<128, 256>>>(wf01,          gatW1, 128 * 256);
    copy_kernel<<<128, 256>>>(wf01 + 32768,  fcW0,  128 * 256);
    copy_kernel<<<64,  256>>>(wkl0,          shW0,  128 * 128);
    copy_kernel<<<64,  256>>>(wkl0 + 16384,  scW0,  128 * 128);
    copy_kernel<<<16,  256>>>(wkl1,          shW1,  64 * 64);
    copy_kernel<<<16,  256>>>(wkl1 + 4096,   scW1,  64 * 64);

    // ---- layer 0 ----
    sd_kernel<<<(N_NODES * HEADS * 32 + 255) / 256, 256>>>(xw0, asrc0, adst0, s, d, 64);
    gat_kernel<64><<<n, 256>>>(csr, off, s, d, xw0, gatb0, h0);

    // ---- fused xw1 + z0 (both consume h0, K=256) ----
    gemm_mma_kernel<128><<<dim3(GX, 2), 256>>>(h0, wf01, n, 256, 128,
                                               xw1, nullptr, 0, 128,
                                               z0, fcb0, 1, 128);

    // ---- layer 1 ----
    sd_kernel<<<(N_NODES * HEADS * 32 + 255) / 256, 256>>>(xw1, asrc1, adst1, s, d, 32);
    gat_kernel<32><<<n, 128>>>(csr, off, s, d, xw1, gatb1, h1);

    // ---- z1 (K=128, N=64) ----
    gemm_mma_kernel<64><<<dim3(GX, 1), 256>>>(h1, fcW1, n, 128, 1 << 30,
                                              z1, fcb1, 1, 64,
                                              nullptr, nullptr, 0, 0);

    // ---- fused k0 + l0 (both consume z0, K=128, transposed stores) ----
    gemm_mma_kernel<128><<<dim3(GX, 2), 256>>>(z0, wkl0, n, 128, 128,
                                               k0, shb0, 2, n,
                                               l0, scb0, 3, n);

    // ---- fused k1 + l1 (both consume z1, K=64, transposed stores) ----
    gemm_mma_kernel<128><<<dim3(GX, 1), 256>>>(z1, wkl1, n, 64, 64,
                                               k1, shb1, 2, n,
                                               l1, scb1, 3, n);

    // ---- fused kl_fix + theta ----
    theta_kernel<<<(128 * n + 255) / 256, 256>>>(k0, l0, eps0, theta0, 128 * n);
    theta_kernel<<<(64  * n + 255) / 256, 256>>>(k1, l1, eps1, theta1, 64 * n);
}

// round 8
// speedup vs baseline: 1.2446x; 1.2126x over previous
#include <cuda_runtime.h>
#include <math.h>
#include <stdint.h>

#define N_NODES 20000
#define NE      320000
#define ET      (NE + N_NODES)
#define HEADS   4

// ---------------- scratch (device globals; no allocation) ----------------
static __device__ float g_xw0[(size_t)N_NODES * 256];
static __device__ float g_h0 [(size_t)N_NODES * 256];
static __device__ float g_xw1[(size_t)N_NODES * 128];
static __device__ float g_h1 [(size_t)N_NODES * 128];
static __device__ float g_z0 [(size_t)N_NODES * 128];
static __device__ float g_z1 [(size_t)N_NODES * 64];
static __device__ float g_s  [N_NODES * 4];
static __device__ float g_d  [N_NODES * 4];
static __device__ int   g_cnt[N_NODES];
static __device__ int   g_cur[N_NODES];
static __device__ int   g_off[N_NODES + 1];
static __device__ int   g_csr[ET];
static __device__ float g_wf01[256 * 256];   // [gatW1 ; fcW0]
static __device__ float g_wkl0[256 * 128];   // [shW0 ; scW0]
static __device__ float g_wkl1[128 * 64];    // [shW1 ; scW1]

// ---------------- helpers ----------------
__device__ __forceinline__ float softplusf(float x) {
    return x > 20.f ? x : log1pf(__expf(x));
}
__device__ __forceinline__ void edge_uv(const int* __restrict__ ei, int e, int& u, int& v) {
    if (e < NE) { u = ei[e]; v = ei[NE + e]; }
    else        { u = v = e - NE; }   // self loops appended
}
__device__ __forceinline__ float tf32_round(float x) {
    uint32_t u;
    asm("cvt.rna.tf32.f32 %0, %1;" : "=r"(u) : "f"(x));
    return __uint_as_float(u);
}
__device__ __forceinline__ void split4(float4 v, float4& h, float4& l) {
    h.x = tf32_round(v.x); l.x = tf32_round(v.x - h.x);
    h.y = tf32_round(v.y); l.y = tf32_round(v.y - h.y);
    h.z = tf32_round(v.z); l.z = tf32_round(v.z - h.z);
    h.w = tf32_round(v.w); l.w = tf32_round(v.w - h.w);
}
__device__ __forceinline__ void mma8(float* c, const float* a, const float* b) {
    asm volatile(
        "mma.sync.aligned.m16n8k8.row.col.f32.tf32.tf32.f32 "
        "{%0,%1,%2,%3}, {%4,%5,%6,%7}, {%8,%9}, {%0,%1,%2,%3};"
        : "+f"(c[0]), "+f"(c[1]), "+f"(c[2]), "+f"(c[3])
        : "r"(__float_as_uint(a[0])), "r"(__float_as_uint(a[1])),
          "r"(__float_as_uint(a[2])), "r"(__float_as_uint(a[3])),
          "r"(__float_as_uint(b[0])), "r"(__float_as_uint(b[1])));
}

// ---------------- simple device copy (graph-safe weight concat) ----------------
__global__ void copy_kernel(float* __restrict__ dst, const float* __restrict__ src, int count) {
    int i = blockIdx.x * blockDim.x + threadIdx.x;
    if (i < count) dst[i] = src[i];
}

// ================= CSR build (group edges by dst) =================
__global__ void zero_cnt_kernel(int* __restrict__ cnt) {
    int i = blockIdx.x * blockDim.x + threadIdx.x;
    if (i < N_NODES) cnt[i] = 0;
}

__global__ void hist_kernel(const int* __restrict__ ei, int* __restrict__ cnt) {
    int e = blockIdx.x * blockDim.x + threadIdx.x;
    if (e >= ET) return;
    int u, v; edge_uv(ei, e, u, v);
    (void)u;
    atomicAdd(&cnt[v], 1);
}

__global__ void scan_kernel(const int* __restrict__ cnt, int* __restrict__ off,
                            int* __restrict__ cur) {
    const int CHUNK = (N_NODES + 1023) / 1024;   // 20
    __shared__ int ts[1024];
    int tid = threadIdx.x;
    int base = tid * CHUNK;
    int s = 0;
    for (int i = 0; i < CHUNK; i++) {
        int idx = base + i;
        if (idx < N_NODES) s += cnt[idx];
    }
    ts[tid] = s;
    __syncthreads();
    for (int o = 1; o < 1024; o <<= 1) {
        int v = (tid >= o) ? ts[tid - o] : 0;
        __syncthreads();
        ts[tid] += v;
        __syncthreads();
    }
    int run = (tid > 0) ? ts[tid - 1] : 0;
    for (int i = 0; i < CHUNK; i++) {
        int idx = base + i;
        if (idx < N_NODES) {
            off[idx] = run;
            run += cnt[idx];
            cur[idx] = 0;
        }
    }
    if (tid == (N_NODES - 1) / CHUNK) off[N_NODES] = run;
}

__global__ void scatter_kernel(const int* __restrict__ ei, const int* __restrict__ off,
                               int* __restrict__ cur, int* __restrict__ csr) {
    int e = blockIdx.x * blockDim.x + threadIdx.x;
    if (e >= ET) return;
    int u, v; edge_uv(ei, e, u, v);
    int pos = off[v] + atomicAdd(&cur[v], 1);
    csr[pos] = u;
}

// ================= 3xTF32 mma.sync GEMM =================
// C[n, Ntot] = A[n,K] * W[Ntot,K]^T; CTA tile 128 x 64, 8 warps (4 along M, 2 along N),
// warp tile 32 x 32. Split-tf32: D = Ahi*Bhi + Ahi*Blo + Alo*Bhi (~fp32 accuracy).
// Output split at nsplit; mode: 0 plain rowmajor, 1 softplus rowmajor,
//                              2 softplus+clip transposed, 3 softplus transposed.
__global__ void __launch_bounds__(256, 2)
gemm_mma_kernel(const float* __restrict__ A, const float* __restrict__ W,
                int n, int K, int nsplit,
                float* __restrict__ outA, const float* __restrict__ biasA, int modeA, int strideA,
                float* __restrict__ outB, const float* __restrict__ biasB, int modeB, int strideB) {
    constexpr int BM = 128, BN = 64, BK = 16;
    constexpr int KP = 20;                     // padded row stride (floats), float4-aligned
    constexpr int NT = 4;                      // n-tiles (8 cols) per warp (32 cols)
    constexpr int AF4 = BM * BK / 4 / 256;     // 2
    constexpr int BF4 = BN * BK / 4 / 256;     // 1

    __shared__ __align__(16) float Ah[BM * KP], Al[BM * KP];
    __shared__ __align__(16) float Bh[BN * KP], Bl[BN * KP];

    const int tid = threadIdx.x;
    const int wid = tid >> 5, lane = tid & 31;
    const int gr = lane >> 2, tig = lane & 3;
    const int warpM = (wid & 3) * 32;
    const int warpN = (wid >> 2) * 32;
    const int bi = blockIdx.x * BM;
    const int bj = blockIdx.y * BN;

    float acc[2][NT][4];
#pragma unroll
    for (int mt = 0; mt < 2; mt++)
#pragma unroll
        for (int nt = 0; nt < NT; nt++)
#pragma unroll
            for (int q = 0; q < 4; q++) acc[mt][nt][q] = 0.f;

    const int nchunk = K / BK;

    // per-thread global load slots
    int arows[AF4], aqs[AF4]; bool avs[AF4];
#pragma unroll
    for (int i = 0; i < AF4; i++) {
        int idx = tid + i * 256;
        arows[i] = idx >> 2; aqs[i] = idx & 3;
        avs[i] = (bi + arows[i]) < n;
    }
    const int brow = tid >> 2, bq = tid & 3;   // BF4 == 1

    float4 apre[AF4], bpre;
#pragma unroll
    for (int i = 0; i < AF4; i++)
        apre[i] = avs[i] ? *(const float4*)(A + (size_t)(bi + arows[i]) * K + aqs[i] * 4)
                         : make_float4(0.f, 0.f, 0.f, 0.f);
    bpre = *(const float4*)(W + (size_t)(bj + brow) * K + bq * 4);

    for (int c = 0; c < nchunk; c++) {
        // store current chunk (split hi/lo)
#pragma unroll
        for (int i = 0; i < AF4; i++) {
            float4 h, l; split4(apre[i], h, l);
            *(float4*)&Ah[arows[i] * KP + aqs[i] * 4] = h;
            *(float4*)&Al[arows[i] * KP + aqs[i] * 4] = l;
        }
        {
            float4 h, l; split4(bpre, h, l);
            *(float4*)&Bh[brow * KP + bq * 4] = h;
            *(float4*)&Bl[brow * KP + bq * 4] = l;
        }
        __syncthreads();

        // prefetch next chunk
        if (c + 1 < nchunk) {
            int k0 = (c + 1) * BK;
#pragma unroll
            for (int i = 0; i < AF4; i++)
                apre[i] = avs[i] ? *(const float4*)(A + (size_t)(bi + arows[i]) * K + k0 + aqs[i] * 4)
                                 : make_float4(0.f, 0.f, 0.f, 0.f);
            bpre = *(const float4*)(W + (size_t)(bj + brow) * K + k0 + bq * 4);
        }

        // compute: 2 k8 steps
#pragma unroll
        for (int kb = 0; kb < BK; kb += 8) {
            float ah[2][4], al[2][4];
#pragma unroll
            for (int mt = 0; mt < 2; mt++) {
                int r0 = (warpM + mt * 16 + gr) * KP + kb + tig;
                int r1 = (warpM + mt * 16 + gr + 8) * KP + kb + tig;
                ah[mt][0] = Ah[r0];     ah[mt][1] = Ah[r1];
                ah[mt][2] = Ah[r0 + 4]; ah[mt][3] = Ah[r1 + 4];
                al[mt][0] = Al[r0];     al[mt][1] = Al[r1];
                al[mt][2] = Al[r0 + 4]; al[mt][3] = Al[r1 + 4];
            }
#pragma unroll
            for (int nt = 0; nt < NT; nt++) {
                int b0 = (warpN + nt * 8 + gr) * KP + kb + tig;
                float bh[2] = {Bh[b0], Bh[b0 + 4]};
                float bl[2] = {Bl[b0], Bl[b0 + 4]};
#pragma unroll
                for (int mt = 0; mt < 2; mt++) {
                    mma8(acc[mt][nt], ah[mt], bh);
                    mma8(acc[mt][nt], ah[mt], bl);
                    mma8(acc[mt][nt], al[mt], bh);
                }
            }
        }
        __syncthreads();
    }

    // ---- epilogue ----
#pragma unroll
    for (int mt = 0; mt < 2; mt++) {
#pragma unroll
        for (int nt = 0; nt < NT; nt++) {
#pragma unroll
            for (int half = 0; half < 2; half++) {       // c0/c1 then c2/c3
                int row = bi + warpM + mt * 16 + gr + half * 8;
                if (row >= n) continue;
#pragma unroll
                for (int p = 0; p < 2; p++) {
                    int jj = bj + warpN + nt * 8 + 2 * tig + p;
                    float v = acc[mt][nt][half * 2 + p];
                    float* o; const float* bp; int mode, stride, j;
                    if (jj < nsplit) { o = outA; bp = biasA; mode = modeA; stride = strideA; j = jj; }
                    else             { o = outB; bp = biasB; mode = modeB; stride = strideB; j = jj - nsplit; }
                    v += bp ? bp[j] : 0.f;
                    if (mode != 0) v = softplusf(v);
                    if (mode == 2) v = fminf(fmaxf(v, 0.1f), 1000.f);
                    if (mode >= 2) o[(size_t)j * stride + row] = v;
                    else           o[(size_t)row * stride + j] = v;
                }
            }
        }
    }
}

// ---------------- attention source/dest scores: one warp per (node, head) ----------------
__global__ void sd_kernel(const float* __restrict__ xw,
                          const float* __restrict__ asrc, const float* __restrict__ adst,
                          float* __restrict__ s, float* __restrict__ d, int C) {
    int warp = (blockIdx.x * blockDim.x + threadIdx.x) >> 5;
    int lane = threadIdx.x & 31;
    if (warp >= N_NODES * HEADS) return;
    int node = warp >> 2, h = warp & 3;
    const float* base = xw + (size_t)node * HEADS * C + h * C;
    float ss = 0.f, dd = 0.f;
    for (int c = lane; c < C; c += 32) {
        float v = base[c];
        ss += v * asrc[h * C + c];
        dd += v * adst[h * C + c];
    }
#pragma unroll
    for (int o = 16; o; o >>= 1) {
        ss += __shfl_down_sync(0xffffffffu, ss, o);
        dd += __shfl_down_sync(0xffffffffu, dd, o);
    }
    if (lane == 0) { s[warp] = ss; d[warp] = dd; }
}

// ================= fused per-node GAT softmax + aggregation =================
template <int C>
__global__ void gat_kernel(const int* __restrict__ csr, const int* __restrict__ off,
                           const float* __restrict__ s, const float* __restrict__ d,
                           const float* __restrict__ xw, const float* __restrict__ bias,
                           float* __restrict__ out) {
    constexpr int HC = 4 * C;
    const int v = blockIdx.x;
    const int tid = threadIdx.x;
    const int h = tid / C;
    const int c = tid - h * C;           // in-head lane 0..C-1
    const int beg = off[v], end = off[v + 1];

    __shared__ float red[HC];
    __shared__ float mh[4], inv[4];

    const float dv = d[v * 4 + h];

    float lmax = -INFINITY;
    for (int j = beg + c; j < end; j += C) {
        int u = csr[j];
        float e = s[u * 4 + h] + dv;
        e = e > 0.f ? e : 0.2f * e;
        lmax = fmaxf(lmax, e);
    }
    red[tid] = lmax;
    __syncthreads();
    if (tid < 4) {
        float m = -INFINITY;
        for (int i = 0; i < C; i++) m = fmaxf(m, red[tid * C + i]);
        mh[tid] = m;
    }
    __syncthreads();
    const float m = mh[h];

    float lsum = 0.f;
    for (int j = beg + c; j < end; j += C) {
        int u = csr[j];
        float e = s[u * 4 + h] + dv;
        e = e > 0.f ? e : 0.2f * e;
        lsum += __expf(e - m);
    }
    red[tid] = lsum;
    __syncthreads();
    if (tid < 4) {
        float sm = 0.f;
        for (int i = 0; i < C; i++) sm += red[tid * C + i];
        inv[tid] = 1.f / (sm + 1e-16f);
    }
    __syncthreads();
    const float invden = inv[h];

    float acc = 0.f;
    for (int j = beg; j < end; j++) {
        int u = csr[j];
        float e = s[u * 4 + h] + dv;
        e = e > 0.f ? e : 0.2f * e;
        float w = __expf(e - m) * invden;
        acc = fmaf(w, xw[(size_t)u * HC + tid], acc);
    }
    out[(size_t)v * HC + tid] = acc + bias[tid];
}

// ---------------- fused kl_fix + theta ----------------
__global__ void theta_kernel(const float* __restrict__ k, float* __restrict__ l,
                             const float* __restrict__ eps, float* __restrict__ th, int ZN) {
    int i = blockIdx.x * blockDim.x + threadIdx.x;
    if (i >= ZN) return;
    float kk = k[i];
    float invk = 1.f / kk;
    float ll = fmaxf(l[i], 2.2e-10f) * expf(-lgammaf(1.f + invk));
    l[i] = ll;
    float acc = 0.f;
#pragma unroll
    for (int s = 0; s < 10; s++) {
        float ep = eps[(size_t)s * ZN + i];
        float t = fmaxf(1.f - ep, 2.2e-10f);
        float nl = -__logf(t);
        acc += __powf(nl, invk);
    }
    float theta = ll * acc * 0.1f;
    th[i] = fminf(fmaxf(theta, 2.2e-10f), 1000.f);
}

// ---------------- host launch ----------------
template <typename T>
static float* symaddrf(T& sym) { void* p = nullptr; cudaGetSymbolAddress(&p, sym); return (float*)p; }
template <typename T>
static int* symaddri(T& sym) { void* p = nullptr; cudaGetSymbolAddress(&p, sym); return (int*)p; }

extern "C" void kernel_launch(void* const* d_in, const int* in_sizes, int n_in,
                              void* d_out, int out_size) {
    const float* x     = (const float*)d_in[0];
    const int*   ei    = (const int*)  d_in[1];
    const float* gatW0 = (const float*)d_in[2];
    const float* asrc0 = (const float*)d_in[3];
    const float* adst0 = (const float*)d_in[4];
    const float* gatb0 = (const float*)d_in[5];
    const float* fcW0  = (const float*)d_in[6];
    const float* fcb0  = (const float*)d_in[7];
    const float* shW0  = (const float*)d_in[8];
    const float* shb0  = (const float*)d_in[9];
    const float* scW0  = (const float*)d_in[10];
    const float* scb0  = (const float*)d_in[11];
    const float* gatW1 = (const float*)d_in[12];
    const float* asrc1 = (const float*)d_in[13];
    const float* adst1 = (const float*)d_in[14];
    const float* gatb1 = (const float*)d_in[15];
    const float* fcW1  = (const float*)d_in[16];
    const float* fcb1  = (const float*)d_in[17];
    const float* shW1  = (const float*)d_in[18];
    const float* shb1  = (const float*)d_in[19];
    const float* scW1  = (const float*)d_in[20];
    const float* scb1  = (const float*)d_in[21];
    const float* eps0  = (const float*)d_in[22];
    const float* eps1  = (const float*)d_in[23];

    const int n = N_NODES;
    float* out = (float*)d_out;
    float* theta0 = out;
    float* theta1 = theta0 + (size_t)128 * n;
    float* k0     = theta1 + (size_t)64  * n;
    float* k1     = k0     + (size_t)128 * n;
    float* l0     = k1     + (size_t)64  * n;
    float* l1     = l0     + (size_t)128 * n;

    float* xw0 = symaddrf(g_xw0);
    float* h0  = symaddrf(g_h0);
    float* xw1 = symaddrf(g_xw1);
    float* h1  = symaddrf(g_h1);
    float* z0  = symaddrf(g_z0);
    float* z1  = symaddrf(g_z1);
    float* s   = symaddrf(g_s);
    float* d   = symaddrf(g_d);
    float* wf01 = symaddrf(g_wf01);
    float* wkl0 = symaddrf(g_wkl0);
    float* wkl1 = symaddrf(g_wkl1);
    int* cnt = symaddri(g_cnt);
    int* cur = symaddri(g_cur);
    int* off = symaddri(g_off);
    int* csr = symaddri(g_csr);

    const int EB = (ET + 255) / 256;
    const int GX = (n + 127) / 128;       // 157 row tiles

    // ---- CSR build; xw0 GEMM at launch index 3 (profiled) ----
    zero_cnt_kernel<<<(n + 255) / 256, 256>>>(cnt);                                   // 0
    hist_kernel<<<EB, 256>>>(ei, cnt);                                                // 1
    scan_kernel<<<1, 1024>>>(cnt, off, cur);                                          // 2
    gemm_mma_kernel<<<dim3(GX, 4), 256>>>(x, gatW0, n, 256, 1 << 30,
                                          xw0, nullptr, 0, 256,
                                          nullptr, nullptr, 0, 0);                     // 3 (profiled)
    scatter_kernel<<<EB, 256>>>(ei, off, cur, csr);                                   // 4

    // ---- weight concats (device copies; graph-safe) ----
    copy_kernel<<<128, 256>>>(wf01,          gatW1, 128 * 256);
    copy_kernel<<<128, 256>>>(wf01 + 32768,  fcW0,  128 * 256);
    copy_kernel<<<64,  256>>>(wkl0,          shW0,  128 * 128);
    copy_kernel<<<64,  256>>>(wkl0 + 16384,  scW0,  128 * 128);
    copy_kernel<<<16,  256>>>(wkl1,          shW1,  64 * 64);
    copy_kernel<<<16,  256>>>(wkl1 + 4096,   scW1,  64 * 64);

    // ---- layer 0 ----
    sd_kernel<<<(N_NODES * HEADS * 32 + 255) / 256, 256>>>(xw0, asrc0, adst0, s, d, 64);
    gat_kernel<64><<<n, 256>>>(csr, off, s, d, xw0, gatb0, h0);

    // ---- fused xw1 + z0 (both consume h0, K=256, Ntot=256) ----
    gemm_mma_kernel<<<dim3(GX, 4), 256>>>(h0, wf01, n, 256, 128,
                                          xw1, nullptr, 0, 128,
                                          z0, fcb0, 1, 128);

    // ---- layer 1 ----
    sd_kernel<<<(N_NODES * HEADS * 32 + 255) / 256, 256>>>(xw1, asrc1, adst1, s, d, 32);
    gat_kernel<32><<<n, 128>>>(csr, off, s, d, xw1, gatb1, h1);

    // ---- z1 (K=128, Ntot=64) ----
    gemm_mma_kernel<<<dim3(GX, 1), 256>>>(h1, fcW1, n, 128, 1 << 30,
                                          z1, fcb1, 1, 64,
                                          nullptr, nullptr, 0, 0);

    // ---- fused k0 + l0 (both consume z0, K=128, Ntot=256, transposed stores) ----
    gemm_mma_kernel<<<dim3(GX, 4), 256>>>(z0, wkl0, n, 128, 128,
                                          k0, shb0, 2, n,
                                          l0, scb0, 3, n);

    // ---- fused k1 + l1 (both consume z1, K=64, Ntot=128, transposed stores) ----
    gemm_mma_kernel<<<dim3(GX, 2), 256>>>(z1, wkl1, n, 64, 64,
                                          k1, shb1, 2, n,
                                          l1, scb1, 3, n);

    // ---- fused kl_fix + theta ----
    theta_kernel<<<(128 * n + 255) / 256, 256>>>(k0, l0, eps0, theta0, 128 * n);
    theta_kernel<<<(64  * n + 255) / 256, 256>>>(k1, l1, eps1, theta1, 64 * n);
}

// round 9
// speedup vs baseline: 1.3172x; 1.0584x over previous
#include <cuda_runtime.h>
#include <math.h>
#include <stdint.h>

#define N_NODES 20000
#define NE      320000
#define ET      (NE + N_NODES)
#define HEADS   4

// ---------------- scratch (device globals; no allocation) ----------------
static __device__ float g_xw0[(size_t)N_NODES * 256];
static __device__ float g_h0 [(size_t)N_NODES * 256];
static __device__ float g_xw1[(size_t)N_NODES * 128];
static __device__ float g_h1 [(size_t)N_NODES * 128];
static __device__ float g_z0 [(size_t)N_NODES * 128];
static __device__ float g_z1 [(size_t)N_NODES * 64];
static __device__ float g_s  [N_NODES * 4];
static __device__ float g_d  [N_NODES * 4];
static __device__ int   g_cnt[N_NODES];
static __device__ int   g_cur[N_NODES];
static __device__ int   g_off[N_NODES + 1];
static __device__ int   g_csr[ET];
static __device__ float g_wf01[256 * 256];   // [gatW1 ; fcW0]
static __device__ float g_wkl0[256 * 128];   // [shW0 ; scW0]
static __device__ float g_wkl1[128 * 64];    // [shW1 ; scW1]

// ---------------- helpers ----------------
__device__ __forceinline__ float softplusf(float x) {
    return x > 20.f ? x : log1pf(__expf(x));
}
__device__ __forceinline__ void edge_uv(const int* __restrict__ ei, int e, int& u, int& v) {
    if (e < NE) { u = ei[e]; v = ei[NE + e]; }
    else        { u = v = e - NE; }   // self loops appended
}
__device__ __forceinline__ float tf32_round(float x) {
    uint32_t u;
    asm("cvt.rna.tf32.f32 %0, %1;" : "=r"(u) : "f"(x));
    return __uint_as_float(u);
}
__device__ __forceinline__ void mma8(float* c, const float* a, const float* b) {
    asm volatile(
        "mma.sync.aligned.m16n8k8.row.col.f32.tf32.tf32.f32 "
        "{%0,%1,%2,%3}, {%4,%5,%6,%7}, {%8,%9}, {%0,%1,%2,%3};"
        : "+f"(c[0]), "+f"(c[1]), "+f"(c[2]), "+f"(c[3])
        : "r"(__float_as_uint(a[0])), "r"(__float_as_uint(a[1])),
          "r"(__float_as_uint(a[2])), "r"(__float_as_uint(a[3])),
          "r"(__float_as_uint(b[0])), "r"(__float_as_uint(b[1])));
}

// ---------------- simple device copy (graph-safe weight concat) ----------------
__global__ void copy_kernel(float* __restrict__ dst, const float* __restrict__ src, int count) {
    int i = blockIdx.x * blockDim.x + threadIdx.x;
    if (i < count) dst[i] = src[i];
}

// ================= CSR build (group edges by dst) =================
__global__ void zero_cnt_kernel(int* __restrict__ cnt) {
    int i = blockIdx.x * blockDim.x + threadIdx.x;
    if (i < N_NODES) cnt[i] = 0;
}

__global__ void hist_kernel(const int* __restrict__ ei, int* __restrict__ cnt) {
    int e = blockIdx.x * blockDim.x + threadIdx.x;
    if (e >= ET) return;
    int u, v; edge_uv(ei, e, u, v);
    (void)u;
    atomicAdd(&cnt[v], 1);
}

__global__ void scan_kernel(const int* __restrict__ cnt, int* __restrict__ off,
                            int* __restrict__ cur) {
    const int CHUNK = (N_NODES + 1023) / 1024;   // 20
    __shared__ int ts[1024];
    int tid = threadIdx.x;
    int base = tid * CHUNK;
    int s = 0;
    for (int i = 0; i < CHUNK; i++) {
        int idx = base + i;
        if (idx < N_NODES) s += cnt[idx];
    }
    ts[tid] = s;
    __syncthreads();
    for (int o = 1; o < 1024; o <<= 1) {
        int v = (tid >= o) ? ts[tid - o] : 0;
        __syncthreads();
        ts[tid] += v;
        __syncthreads();
    }
    int run = (tid > 0) ? ts[tid - 1] : 0;
    for (int i = 0; i < CHUNK; i++) {
        int idx = base + i;
        if (idx < N_NODES) {
            off[idx] = run;
            run += cnt[idx];
            cur[idx] = 0;
        }
    }
    if (tid == (N_NODES - 1) / CHUNK) off[N_NODES] = run;
}

__global__ void scatter_kernel(const int* __restrict__ ei, const int* __restrict__ off,
                               int* __restrict__ cur, int* __restrict__ csr) {
    int e = blockIdx.x * blockDim.x + threadIdx.x;
    if (e >= ET) return;
    int u, v; edge_uv(ei, e, u, v);
    int pos = off[v] + atomicAdd(&cur[v], 1);
    csr[pos] = u;
}

// ================= 3xTF32 mma.sync GEMM (raw f32 in smem, register split) =========
// C[n, Ntot] = A[n,K] * W[Ntot,K]^T; CTA tile 128 x 64, 8 warps (4 along M, 2 along N),
// warp tile 32 x 32. D = Ahi*Bhi + Ahi*Blo + Alo*Bhi (~fp32 accuracy); hi = rna_tf32(v),
// lo = v - hi fed raw (HW truncation of lo costs ~2^-23 rel — negligible).
// Output split at nsplit; mode: 0 plain rowmajor, 1 softplus rowmajor,
//                              2 softplus+clip transposed, 3 softplus transposed.
__global__ void __launch_bounds__(256, 2)
gemm_mma_kernel(const float* __restrict__ A, const float* __restrict__ W,
                int n, int K, int nsplit,
                float* __restrict__ outA, const float* __restrict__ biasA, int modeA, int strideA,
                float* __restrict__ outB, const float* __restrict__ biasB, int modeB, int strideB) {
    constexpr int BM = 128, BN = 64, BK = 16;
    constexpr int KP = 20;                     // padded row stride (floats), float4-aligned
    constexpr int NT = 4;                      // n-tiles (8 cols) per warp (32 cols)
    constexpr int AF4 = BM * BK / 4 / 256;     // 2

    __shared__ __align__(16) float As[BM * KP];
    __shared__ __align__(16) float Bs[BN * KP];

    const int tid = threadIdx.x;
    const int wid = tid >> 5, lane = tid & 31;
    const int gr = lane >> 2, tig = lane & 3;
    const int warpM = (wid & 3) * 32;
    const int warpN = (wid >> 2) * 32;
    const int bi = blockIdx.x * BM;
    const int bj = blockIdx.y * BN;

    float acc[2][NT][4];
#pragma unroll
    for (int mt = 0; mt < 2; mt++)
#pragma unroll
        for (int nt = 0; nt < NT; nt++)
#pragma unroll
            for (int q = 0; q < 4; q++) acc[mt][nt][q] = 0.f;

    const int nchunk = K / BK;

    // per-thread global load slots
    int arows[AF4], aqs[AF4]; bool avs[AF4];
#pragma unroll
    for (int i = 0; i < AF4; i++) {
        int idx = tid + i * 256;
        arows[i] = idx >> 2; aqs[i] = idx & 3;
        avs[i] = (bi + arows[i]) < n;
    }
    const int brow = tid >> 2, bq = tid & 3;

    float4 apre[AF4], bpre;
#pragma unroll
    for (int i = 0; i < AF4; i++)
        apre[i] = avs[i] ? *(const float4*)(A + (size_t)(bi + arows[i]) * K + aqs[i] * 4)
                         : make_float4(0.f, 0.f, 0.f, 0.f);
    bpre = *(const float4*)(W + (size_t)(bj + brow) * K + bq * 4);

    for (int c = 0; c < nchunk; c++) {
        // store current chunk (raw f32, no split)
#pragma unroll
        for (int i = 0; i < AF4; i++)
            *(float4*)&As[arows[i] * KP + aqs[i] * 4] = apre[i];
        *(float4*)&Bs[brow * KP + bq * 4] = bpre;
        __syncthreads();

        // prefetch next chunk
        if (c + 1 < nchunk) {
            int k0 = (c + 1) * BK;
#pragma unroll
            for (int i = 0; i < AF4; i++)
                apre[i] = avs[i] ? *(const float4*)(A + (size_t)(bi + arows[i]) * K + k0 + aqs[i] * 4)
                                 : make_float4(0.f, 0.f, 0.f, 0.f);
            bpre = *(const float4*)(W + (size_t)(bj + brow) * K + k0 + bq * 4);
        }

        // compute: 2 k8 steps
#pragma unroll
        for (int kb = 0; kb < BK; kb += 8) {
            float ah[2][4], al[2][4];
#pragma unroll
            for (int mt = 0; mt < 2; mt++) {
                int r0 = (warpM + mt * 16 + gr) * KP + kb + tig;
                int r1 = r0 + 8 * KP;
                float raw0 = As[r0], raw1 = As[r1], raw2 = As[r0 + 4], raw3 = As[r1 + 4];
                ah[mt][0] = tf32_round(raw0); al[mt][0] = raw0 - ah[mt][0];
                ah[mt][1] = tf32_round(raw1); al[mt][1] = raw1 - ah[mt][1];
                ah[mt][2] = tf32_round(raw2); al[mt][2] = raw2 - ah[mt][2];
                ah[mt][3] = tf32_round(raw3); al[mt][3] = raw3 - ah[mt][3];
            }
#pragma unroll
            for (int nt = 0; nt < NT; nt++) {
                int b0 = (warpN + nt * 8 + gr) * KP + kb + tig;
                float braw0 = Bs[b0], braw1 = Bs[b0 + 4];
                float bh[2], bl[2];
                bh[0] = tf32_round(braw0); bl[0] = braw0 - bh[0];
                bh[1] = tf32_round(braw1); bl[1] = braw1 - bh[1];
#pragma unroll
                for (int mt = 0; mt < 2; mt++) {
                    mma8(acc[mt][nt], ah[mt], bh);
                    mma8(acc[mt][nt], ah[mt], bl);
                    mma8(acc[mt][nt], al[mt], bh);
                }
            }
        }
        __syncthreads();
    }

    // ---- epilogue ----
#pragma unroll
    for (int mt = 0; mt < 2; mt++) {
#pragma unroll
        for (int nt = 0; nt < NT; nt++) {
#pragma unroll
            for (int half = 0; half < 2; half++) {       // c0/c1 then c2/c3
                int row = bi + warpM + mt * 16 + gr + half * 8;
                if (row >= n) continue;
#pragma unroll
                for (int p = 0; p < 2; p++) {
                    int jj = bj + warpN + nt * 8 + 2 * tig + p;
                    float v = acc[mt][nt][half * 2 + p];
                    float* o; const float* bp; int mode, stride, j;
                    if (jj < nsplit) { o = outA; bp = biasA; mode = modeA; stride = strideA; j = jj; }
                    else             { o = outB; bp = biasB; mode = modeB; stride = strideB; j = jj - nsplit; }
                    v += bp ? bp[j] : 0.f;
                    if (mode != 0) v = softplusf(v);
                    if (mode == 2) v = fminf(fmaxf(v, 0.1f), 1000.f);
                    if (mode >= 2) o[(size_t)j * stride + row] = v;
                    else           o[(size_t)row * stride + j] = v;
                }
            }
        }
    }
}

// ---------------- attention source/dest scores: one warp per (node, head) ----------------
__global__ void sd_kernel(const float* __restrict__ xw,
                          const float* __restrict__ asrc, const float* __restrict__ adst,
                          float* __restrict__ s, float* __restrict__ d, int C) {
    int warp = (blockIdx.x * blockDim.x + threadIdx.x) >> 5;
    int lane = threadIdx.x & 31;
    if (warp >= N_NODES * HEADS) return;
    int node = warp >> 2, h = warp & 3;
    const float* base = xw + (size_t)node * HEADS * C + h * C;
    float ss = 0.f, dd = 0.f;
    for (int c = lane; c < C; c += 32) {
        float v = base[c];
        ss += v * asrc[h * C + c];
        dd += v * adst[h * C + c];
    }
#pragma unroll
    for (int o = 16; o; o >>= 1) {
        ss += __shfl_down_sync(0xffffffffu, ss, o);
        dd += __shfl_down_sync(0xffffffffu, dd, o);
    }
    if (lane == 0) { s[warp] = ss; d[warp] = dd; }
}

// ================= fused per-node GAT softmax + aggregation =================
template <int C>
__global__ void gat_kernel(const int* __restrict__ csr, const int* __restrict__ off,
                           const float* __restrict__ s, const float* __restrict__ d,
                           const float* __restrict__ xw, const float* __restrict__ bias,
                           float* __restrict__ out) {
    constexpr int HC = 4 * C;
    const int v = blockIdx.x;
    const int tid = threadIdx.x;
    const int h = tid / C;
    const int c = tid - h * C;           // in-head lane 0..C-1
    const int beg = off[v], end = off[v + 1];

    __shared__ float red[HC];
    __shared__ float mh[4], inv[4];

    const float dv = d[v * 4 + h];

    float lmax = -INFINITY;
    for (int j = beg + c; j < end; j += C) {
        int u = csr[j];
        float e = s[u * 4 + h] + dv;
        e = e > 0.f ? e : 0.2f * e;
        lmax = fmaxf(lmax, e);
    }
    red[tid] = lmax;
    __syncthreads();
    if (tid < 4) {
        float m = -INFINITY;
        for (int i = 0; i < C; i++) m = fmaxf(m, red[tid * C + i]);
        mh[tid] = m;
    }
    __syncthreads();
    const float m = mh[h];

    float lsum = 0.f;
    for (int j = beg + c; j < end; j += C) {
        int u = csr[j];
        float e = s[u * 4 + h] + dv;
        e = e > 0.f ? e : 0.2f * e;
        lsum += __expf(e - m);
    }
    red[tid] = lsum;
    __syncthreads();
    if (tid < 4) {
        float sm = 0.f;
        for (int i = 0; i < C; i++) sm += red[tid * C + i];
        inv[tid] = 1.f / (sm + 1e-16f);
    }
    __syncthreads();
    const float invden = inv[h];

    float acc = 0.f;
    for (int j = beg; j < end; j++) {
        int u = csr[j];
        float e = s[u * 4 + h] + dv;
        e = e > 0.f ? e : 0.2f * e;
        float w = __expf(e - m) * invden;
        acc = fmaf(w, xw[(size_t)u * HC + tid], acc);
    }
    out[(size_t)v * HC + tid] = acc + bias[tid];
}

// ---------------- fused kl_fix + theta ----------------
__global__ void theta_kernel(const float* __restrict__ k, float* __restrict__ l,
                             const float* __restrict__ eps, float* __restrict__ th, int ZN) {
    int i = blockIdx.x * blockDim.x + threadIdx.x;
    if (i >= ZN) return;
    float kk = k[i];
    float invk = 1.f / kk;
    float ll = fmaxf(l[i], 2.2e-10f) * expf(-lgammaf(1.f + invk));
    l[i] = ll;
    float acc = 0.f;
#pragma unroll
    for (int s = 0; s < 10; s++) {
        float ep = eps[(size_t)s * ZN + i];
        float t = fmaxf(1.f - ep, 2.2e-10f);
        float nl = -__logf(t);
        acc += __powf(nl, invk);
    }
    float theta = ll * acc * 0.1f;
    th[i] = fminf(fmaxf(theta, 2.2e-10f), 1000.f);
}

// ---------------- host launch ----------------
template <typename T>
static float* symaddrf(T& sym) { void* p = nullptr; cudaGetSymbolAddress(&p, sym); return (float*)p; }
template <typename T>
static int* symaddri(T& sym) { void* p = nullptr; cudaGetSymbolAddress(&p, sym); return (int*)p; }

extern "C" void kernel_launch(void* const* d_in, const int* in_sizes, int n_in,
                              void* d_out, int out_size) {
    const float* x     = (const float*)d_in[0];
    const int*   ei    = (const int*)  d_in[1];
    const float* gatW0 = (const float*)d_in[2];
    const float* asrc0 = (const float*)d_in[3];
    const float* adst0 = (const float*)d_in[4];
    const float* gatb0 = (const float*)d_in[5];
    const float* fcW0  = (const float*)d_in[6];
    const float* fcb0  = (const float*)d_in[7];
    const float* shW0  = (const float*)d_in[8];
    const float* shb0  = (const float*)d_in[9];
    const float* scW0  = (const float*)d_in[10];
    const float* scb0  = (const float*)d_in[11];
    const float* gatW1 = (const float*)d_in[12];
    const float* asrc1 = (const float*)d_in[13];
    const float* adst1 = (const float*)d_in[14];
    const float* gatb1 = (const float*)d_in[15];
    const float* fcW1  = (const float*)d_in[16];
    const float* fcb1  = (const float*)d_in[17];
    const float* shW1  = (const float*)d_in[18];
    const float* shb1  = (const float*)d_in[19];
    const float* scW1  = (const float*)d_in[20];
    const float* scb1  = (const float*)d_in[21];
    const float* eps0  = (const float*)d_in[22];
    const float* eps1  = (const float*)d_in[23];

    const int n = N_NODES;
    float* out = (float*)d_out;
    float* theta0 = out;
    float* theta1 = theta0 + (size_t)128 * n;
    float* k0     = theta1 + (size_t)64  * n;
    float* k1     = k0     + (size_t)128 * n;
    float* l0     = k1     + (size_t)64  * n;
    float* l1     = l0     + (size_t)128 * n;

    float* xw0 = symaddrf(g_xw0);
    float* h0  = symaddrf(g_h0);
    float* xw1 = symaddrf(g_xw1);
    float* h1  = symaddrf(g_h1);
    float* z0  = symaddrf(g_z0);
    float* z1  = symaddrf(g_z1);
    float* s   = symaddrf(g_s);
    float* d   = symaddrf(g_d);
    float* wf01 = symaddrf(g_wf01);
    float* wkl0 = symaddrf(g_wkl0);
    float* wkl1 = symaddrf(g_wkl1);
    int* cnt = symaddri(g_cnt);
    int* cur = symaddri(g_cur);
    int* off = symaddri(g_off);
    int* csr = symaddri(g_csr);

    const int EB = (ET + 255) / 256;
    const int GX = (n + 127) / 128;       // 157 row tiles

    // ---- CSR build; xw0 GEMM at launch index 3 (profiled) ----
    zero_cnt_kernel<<<(n + 255) / 256, 256>>>(cnt);                                   // 0
    hist_kernel<<<EB, 256>>>(ei, cnt);                                                // 1
    scan_kernel<<<1, 1024>>>(cnt, off, cur);                                          // 2
    gemm_mma_kernel<<<dim3(GX, 4), 256>>>(x, gatW0, n, 256, 1 << 30,
                                          xw0, nullptr, 0, 256,
                                          nullptr, nullptr, 0, 0);                     // 3 (profiled)
    scatter_kernel<<<EB, 256>>>(ei, off, cur, csr);                                   // 4

    // ---- weight concats (device copies; graph-safe) ----
    copy_kernel<<<128, 256>>>(wf01,          gatW1, 128 * 256);
    copy_kernel<<<128, 256>>>(wf01 + 32768,  fcW0,  128 * 256);
    copy_kernel<<<64,  256>>>(wkl0,          shW0,  128 * 128);
    copy_kernel<<<64,  256>>>(wkl0 + 16384,  scW0,  128 * 128);
    copy_kernel<<<16,  256>>>(wkl1,          shW1,  64 * 64);
    copy_kernel<<<16,  256>>>(wkl1 + 4096,   scW1,  64 * 64);

    // ---- layer 0 ----
    sd_kernel<<<(N_NODES * HEADS * 32 + 255) / 256, 256>>>(xw0, asrc0, adst0, s, d, 64);
    gat_kernel<64><<<n, 256>>>(csr, off, s, d, xw0, gatb0, h0);

    // ---- fused xw1 + z0 (both consume h0, K=256, Ntot=256) ----
    gemm_mma_kernel<<<dim3(GX, 4), 256>>>(h0, wf01, n, 256, 128,
                                          xw1, nullptr, 0, 128,
                                          z0, fcb0, 1, 128);

    // ---- layer 1 ----
    sd_kernel<<<(N_NODES * HEADS * 32 + 255) / 256, 256>>>(xw1, asrc1, adst1, s, d, 32);
    gat_kernel<32><<<n, 128>>>(csr, off, s, d, xw1, gatb1, h1);

    // ---- z1 (K=128, Ntot=64) ----
    gemm_mma_kernel<<<dim3(GX, 1), 256>>>(h1, fcW1, n, 128, 1 << 30,
                                          z1, fcb1, 1, 64,
                                          nullptr, nullptr, 0, 0);

    // ---- fused k0 + l0 (both consume z0, K=128, Ntot=256, transposed stores) ----
    gemm_mma_kernel<<<dim3(GX, 4), 256>>>(z0, wkl0, n, 128, 128,
                                          k0, shb0, 2, n,
                                          l0, scb0, 3, n);

    // ---- fused k1 + l1 (both consume z1, K=64, Ntot=128, transposed stores) ----
    gemm_mma_kernel<<<dim3(GX, 2), 256>>>(z1, wkl1, n, 64, 64,
                                          k1, shb1, 2, n,
                                          l1, scb1, 3, n);

    // ---- fused kl_fix + theta ----
    theta_kernel<<<(128 * n + 255) / 256, 256>>>(k0, l0, eps0, theta0, 128 * n);
    theta_kernel<<<(64  * n + 255) / 256, 256>>>(k1, l1, eps1, theta1, 64 * n);
}

// round 10
// speedup vs baseline: 1.4533x; 1.1033x over previous
#include <cuda_runtime.h>
#include <math.h>
#include <stdint.h>

#define N_NODES 20000
#define NE      320000
#define ET      (NE + N_NODES)
#define HEADS   4

// ---------------- scratch (device globals; no allocation) ----------------
static __device__ float g_xw0[(size_t)N_NODES * 256];
static __device__ float g_h0 [(size_t)N_NODES * 256];
static __device__ float g_xw1[(size_t)N_NODES * 128];
static __device__ float g_h1 [(size_t)N_NODES * 128];
static __device__ float g_z0 [(size_t)N_NODES * 128];
static __device__ float g_z1 [(size_t)N_NODES * 64];
static __device__ float g_s0 [N_NODES * 4];
static __device__ float g_d0 [N_NODES * 4];
static __device__ float g_s1 [N_NODES * 4];
static __device__ float g_d1 [N_NODES * 4];
static __device__ int   g_cnt[N_NODES];
static __device__ int   g_cur[N_NODES];
static __device__ int   g_off[N_NODES + 1];
static __device__ int   g_csr[ET];
static __device__ float g_wf01[256 * 256];   // [gatW1 ; fcW0]
static __device__ float g_wkl0[256 * 128];   // [shW0 ; scW0]
static __device__ float g_wkl1[128 * 64];    // [shW1 ; scW1]

// ---------------- helpers ----------------
__device__ __forceinline__ float softplusf(float x) {
    return x > 20.f ? x : log1pf(__expf(x));
}
__device__ __forceinline__ void edge_uv(const int* __restrict__ ei, int e, int& u, int& v) {
    if (e < NE) { u = ei[e]; v = ei[NE + e]; }
    else        { u = v = e - NE; }   // self loops appended
}
__device__ __forceinline__ float tf32_round(float x) {
    uint32_t u;
    asm("cvt.rna.tf32.f32 %0, %1;" : "=r"(u) : "f"(x));
    return __uint_as_float(u);
}
__device__ __forceinline__ void mma8(float* c, const float* a, const float* b) {
    asm volatile(
        "mma.sync.aligned.m16n8k8.row.col.f32.tf32.tf32.f32 "
        "{%0,%1,%2,%3}, {%4,%5,%6,%7}, {%8,%9}, {%0,%1,%2,%3};"
        : "+f"(c[0]), "+f"(c[1]), "+f"(c[2]), "+f"(c[3])
        : "r"(__float_as_uint(a[0])), "r"(__float_as_uint(a[1])),
          "r"(__float_as_uint(a[2])), "r"(__float_as_uint(a[3])),
          "r"(__float_as_uint(b[0])), "r"(__float_as_uint(b[1])));
}

// ---------------- fused init: zero cnt + all 4 s/d buffers ----------------
__global__ void init_kernel(int* __restrict__ cnt, float* __restrict__ s0,
                            float* __restrict__ d0, float* __restrict__ s1,
                            float* __restrict__ d1) {
    int i = blockIdx.x * blockDim.x + threadIdx.x;
    if (i < N_NODES) cnt[i] = 0;
    if (i < N_NODES * 4) { s0[i] = 0.f; d0[i] = 0.f; s1[i] = 0.f; d1[i] = 0.f; }
}

// ---------------- fused weight concat (one launch) ----------------
__global__ void concat_kernel(float* __restrict__ wf01, float* __restrict__ wkl0,
                              float* __restrict__ wkl1,
                              const float* __restrict__ gatW1, const float* __restrict__ fcW0,
                              const float* __restrict__ shW0, const float* __restrict__ scW0,
                              const float* __restrict__ shW1, const float* __restrict__ scW1) {
    int i = blockIdx.x * blockDim.x + threadIdx.x;
    if (i < 32768) { wf01[i] = gatW1[i]; wf01[32768 + i] = fcW0[i]; }
    if (i < 16384) { wkl0[i] = shW0[i]; wkl0[16384 + i] = scW0[i]; }
    if (i < 4096)  { wkl1[i] = shW1[i]; wkl1[4096 + i] = scW1[i]; }
}

// ================= CSR build (group edges by dst) =================
__global__ void hist_kernel(const int* __restrict__ ei, int* __restrict__ cnt) {
    int e = blockIdx.x * blockDim.x + threadIdx.x;
    if (e >= ET) return;
    int u, v; edge_uv(ei, e, u, v);
    (void)u;
    atomicAdd(&cnt[v], 1);
}

__global__ void scan_kernel(const int* __restrict__ cnt, int* __restrict__ off,
                            int* __restrict__ cur) {
    const int CHUNK = (N_NODES + 1023) / 1024;   // 20
    __shared__ int ts[1024];
    int tid = threadIdx.x;
    int base = tid * CHUNK;
    int s = 0;
    for (int i = 0; i < CHUNK; i++) {
        int idx = base + i;
        if (idx < N_NODES) s += cnt[idx];
    }
    ts[tid] = s;
    __syncthreads();
    for (int o = 1; o < 1024; o <<= 1) {
        int v = (tid >= o) ? ts[tid - o] : 0;
        __syncthreads();
        ts[tid] += v;
        __syncthreads();
    }
    int run = (tid > 0) ? ts[tid - 1] : 0;
    for (int i = 0; i < CHUNK; i++) {
        int idx = base + i;
        if (idx < N_NODES) {
            off[idx] = run;
            run += cnt[idx];
            cur[idx] = 0;
        }
    }
    if (tid == (N_NODES - 1) / CHUNK) off[N_NODES] = run;
}

__global__ void scatter_kernel(const int* __restrict__ ei, const int* __restrict__ off,
                               int* __restrict__ cur, int* __restrict__ csr) {
    int e = blockIdx.x * blockDim.x + threadIdx.x;
    if (e >= ET) return;
    int u, v; edge_uv(ei, e, u, v);
    int pos = off[v] + atomicAdd(&cur[v], 1);
    csr[pos] = u;
}

// ================= 3xTF32 mma.sync GEMM (BK=32, raw f32 smem, register split) ======
// C[n, Ntot] = A[n,K] * W[Ntot,K]^T; CTA tile 128 x 64, 8 warps (4 M x 2 N),
// warp tile 32 x 32. D = Ahi*Bhi + Ahi*Blo + Alo*Bhi (~fp32 accuracy).
// mode: 0 plain rowmajor, 1 softplus rowmajor, 2 softplus+clip transposed,
//       3 softplus transposed, 4 plain rowmajor + GAT s/d accumulation (atomicAdd).
__global__ void __launch_bounds__(256, 2)
gemm_mma_kernel(const float* __restrict__ A, const float* __restrict__ W,
                int n, int K, int nsplit,
                float* __restrict__ outA, const float* __restrict__ biasA, int modeA, int strideA,
                float* __restrict__ outB, const float* __restrict__ biasB, int modeB, int strideB,
                const float* __restrict__ asrcP, const float* __restrict__ adstP,
                float* __restrict__ sOut, float* __restrict__ dOut, int headC) {
    constexpr int BM = 128, BN = 64, BK = 32;
    constexpr int KP = 36;                     // padded row stride (floats); 4*gr+tig walks banks
    constexpr int NT = 4;                      // n-tiles (8 cols) per warp (32 cols)
    constexpr int AF4 = BM * BK / 4 / 256;     // 4
    constexpr int BF4 = BN * BK / 4 / 256;     // 2

    __shared__ __align__(16) float As[BM * KP];
    __shared__ __align__(16) float Bs[BN * KP];

    const int tid = threadIdx.x;
    const int wid = tid >> 5, lane = tid & 31;
    const int gr = lane >> 2, tig = lane & 3;
    const int warpM = (wid & 3) * 32;
    const int warpN = (wid >> 2) * 32;
    const int bi = blockIdx.x * BM;
    const int bj = blockIdx.y * BN;

    float acc[2][NT][4];
#pragma unroll
    for (int mt = 0; mt < 2; mt++)
#pragma unroll
        for (int nt = 0; nt < NT; nt++)
#pragma unroll
            for (int q = 0; q < 4; q++) acc[mt][nt][q] = 0.f;

    const int nchunk = K / BK;

    int arows[AF4], aqs[AF4]; bool avs[AF4];
#pragma unroll
    for (int i = 0; i < AF4; i++) {
        int idx = tid + i * 256;
        arows[i] = idx >> 3; aqs[i] = idx & 7;
        avs[i] = (bi + arows[i]) < n;
    }
    int brows[BF4], bqs[BF4];
#pragma unroll
    for (int i = 0; i < BF4; i++) {
        int idx = tid + i * 256;
        brows[i] = idx >> 3; bqs[i] = idx & 7;
    }

    float4 apre[AF4], bpre[BF4];
#pragma unroll
    for (int i = 0; i < AF4; i++)
        apre[i] = avs[i] ? *(const float4*)(A + (size_t)(bi + arows[i]) * K + aqs[i] * 4)
                         : make_float4(0.f, 0.f, 0.f, 0.f);
#pragma unroll
    for (int i = 0; i < BF4; i++)
        bpre[i] = *(const float4*)(W + (size_t)(bj + brows[i]) * K + bqs[i] * 4);

    for (int c = 0; c < nchunk; c++) {
#pragma unroll
        for (int i = 0; i < AF4; i++)
            *(float4*)&As[arows[i] * KP + aqs[i] * 4] = apre[i];
#pragma unroll
        for (int i = 0; i < BF4; i++)
            *(float4*)&Bs[brows[i] * KP + bqs[i] * 4] = bpre[i];
        __syncthreads();

        if (c + 1 < nchunk) {
            int k0 = (c + 1) * BK;
#pragma unroll
            for (int i = 0; i < AF4; i++)
                apre[i] = avs[i] ? *(const float4*)(A + (size_t)(bi + arows[i]) * K + k0 + aqs[i] * 4)
                                 : make_float4(0.f, 0.f, 0.f, 0.f);
#pragma unroll
            for (int i = 0; i < BF4; i++)
                bpre[i] = *(const float4*)(W + (size_t)(bj + brows[i]) * K + k0 + bqs[i] * 4);
        }

#pragma unroll
        for (int kb = 0; kb < BK; kb += 8) {
            float ah[2][4], al[2][4];
#pragma unroll
            for (int mt = 0; mt < 2; mt++) {
                int r0 = (warpM + mt * 16 + gr) * KP + kb + tig;
                int r1 = r0 + 8 * KP;
                float raw0 = As[r0], raw1 = As[r1], raw2 = As[r0 + 4], raw3 = As[r1 + 4];
                ah[mt][0] = tf32_round(raw0); al[mt][0] = raw0 - ah[mt][0];
                ah[mt][1] = tf32_round(raw1); al[mt][1] = raw1 - ah[mt][1];
                ah[mt][2] = tf32_round(raw2); al[mt][2] = raw2 - ah[mt][2];
                ah[mt][3] = tf32_round(raw3); al[mt][3] = raw3 - ah[mt][3];
            }
#pragma unroll
            for (int nt = 0; nt < NT; nt++) {
                int b0 = (warpN + nt * 8 + gr) * KP + kb + tig;
                float braw0 = Bs[b0], braw1 = Bs[b0 + 4];
                float bh[2], bl[2];
                bh[0] = tf32_round(braw0); bl[0] = braw0 - bh[0];
                bh[1] = tf32_round(braw1); bl[1] = braw1 - bh[1];
#pragma unroll
                for (int mt = 0; mt < 2; mt++) {
                    mma8(acc[mt][nt], ah[mt], bh);
                    mma8(acc[mt][nt], ah[mt], bl);
                    mma8(acc[mt][nt], al[mt], bh);
                }
            }
        }
        __syncthreads();
    }

    // ---- epilogue (segment uniform per warp: nsplit is a multiple of 32) ----
    const int jbase = bj + warpN;
    float* o; const float* bp; int mode, stride, joff;
    if (jbase < nsplit) { o = outA; bp = biasA; mode = modeA; stride = strideA; joff = 0; }
    else                { o = outB; bp = biasB; mode = modeB; stride = strideB; joff = nsplit; }

#pragma unroll
    for (int mt = 0; mt < 2; mt++) {
#pragma unroll
        for (int half = 0; half < 2; half++) {
            int row = bi + warpM + mt * 16 + gr + half * 8;
            if (row >= n) continue;
            float ss = 0.f, dd = 0.f;
#pragma unroll
            for (int nt = 0; nt < NT; nt++) {
#pragma unroll
                for (int p = 0; p < 2; p++) {
                    int jj = jbase + nt * 8 + 2 * tig + p;
                    float v = acc[mt][nt][half * 2 + p];
                    int j = jj - joff;
                    if (mode == 4) {
                        o[(size_t)row * stride + j] = v;
                        ss += v * asrcP[jj];
                        dd += v * adstP[jj];
                    } else {
                        v += bp ? bp[j] : 0.f;
                        if (mode != 0) v = softplusf(v);
                        if (mode == 2) v = fminf(fmaxf(v, 0.1f), 1000.f);
                        if (mode >= 2) o[(size_t)j * stride + row] = v;
                        else           o[(size_t)row * stride + j] = v;
                    }
                }
            }
            if (mode == 4) {
                int h = jbase / headC;       // warp tile lies in exactly one head
                atomicAdd(&sOut[row * 4 + h], ss);
                atomicAdd(&dOut[row * 4 + h], dd);
            }
        }
    }
}

// ================= fused per-node GAT softmax + aggregation =================
template <int C>
__global__ void gat_kernel(const int* __restrict__ csr, const int* __restrict__ off,
                           const float* __restrict__ s, const float* __restrict__ d,
                           const float* __restrict__ xw, const float* __restrict__ bias,
                           float* __restrict__ out) {
    constexpr int HC = 4 * C;
    const int v = blockIdx.x;
    const int tid = threadIdx.x;
    const int h = tid / C;
    const int c = tid - h * C;           // in-head lane 0..C-1
    const int beg = off[v], end = off[v + 1];

    __shared__ float red[HC];
    __shared__ float mh[4], inv[4];

    const float dv = d[v * 4 + h];

    float lmax = -INFINITY;
    for (int j = beg + c; j < end; j += C) {
        int u = csr[j];
        float e = s[u * 4 + h] + dv;
        e = e > 0.f ? e : 0.2f * e;
        lmax = fmaxf(lmax, e);
    }
    red[tid] = lmax;
    __syncthreads();
    if (tid < 4) {
        float m = -INFINITY;
        for (int i = 0; i < C; i++) m = fmaxf(m, red[tid * C + i]);
        mh[tid] = m;
    }
    __syncthreads();
    const float m = mh[h];

    float lsum = 0.f;
    for (int j = beg + c; j < end; j += C) {
        int u = csr[j];
        float e = s[u * 4 + h] + dv;
        e = e > 0.f ? e : 0.2f * e;
        lsum += __expf(e - m);
    }
    red[tid] = lsum;
    __syncthreads();
    if (tid < 4) {
        float sm = 0.f;
        for (int i = 0; i < C; i++) sm += red[tid * C + i];
        inv[tid] = 1.f / (sm + 1e-16f);
    }
    __syncthreads();
    const float invden = inv[h];

    float acc = 0.f;
    for (int j = beg; j < end; j++) {
        int u = csr[j];
        float e = s[u * 4 + h] + dv;
        e = e > 0.f ? e : 0.2f * e;
        float w = __expf(e - m) * invden;
        acc = fmaf(w, xw[(size_t)u * HC + tid], acc);
    }
    out[(size_t)v * HC + tid] = acc + bias[tid];
}

// ---------------- fused kl_fix + theta ----------------
__global__ void theta_kernel(const float* __restrict__ k, float* __restrict__ l,
                             const float* __restrict__ eps, float* __restrict__ th, int ZN) {
    int i = blockIdx.x * blockDim.x + threadIdx.x;
    if (i >= ZN) return;
    float kk = k[i];
    float invk = 1.f / kk;
    float ll = fmaxf(l[i], 2.2e-10f) * expf(-lgammaf(1.f + invk));
    l[i] = ll;
    float acc = 0.f;
#pragma unroll
    for (int s = 0; s < 10; s++) {
        float ep = eps[(size_t)s * ZN + i];
        float t = fmaxf(1.f - ep, 2.2e-10f);
        float nl = -__logf(t);
        acc += __powf(nl, invk);
    }
    float theta = ll * acc * 0.1f;
    th[i] = fminf(fmaxf(theta, 2.2e-10f), 1000.f);
}

// ---------------- host launch ----------------
template <typename T>
static float* symaddrf(T& sym) { void* p = nullptr; cudaGetSymbolAddress(&p, sym); return (float*)p; }
template <typename T>
static int* symaddri(T& sym) { void* p = nullptr; cudaGetSymbolAddress(&p, sym); return (int*)p; }

extern "C" void kernel_launch(void* const* d_in, const int* in_sizes, int n_in,
                              void* d_out, int out_size) {
    const float* x     = (const float*)d_in[0];
    const int*   ei    = (const int*)  d_in[1];
    const float* gatW0 = (const float*)d_in[2];
    const float* asrc0 = (const float*)d_in[3];
    const float* adst0 = (const float*)d_in[4];
    const float* gatb0 = (const float*)d_in[5];
    const float* fcW0  = (const float*)d_in[6];
    const float* fcb0  = (const float*)d_in[7];
    const float* shW0  = (const float*)d_in[8];
    const float* shb0  = (const float*)d_in[9];
    const float* scW0  = (const float*)d_in[10];
    const float* scb0  = (const float*)d_in[11];
    const float* gatW1 = (const float*)d_in[12];
    const float* asrc1 = (const float*)d_in[13];
    const float* adst1 = (const float*)d_in[14];
    const float* gatb1 = (const float*)d_in[15];
    const float* fcW1  = (const float*)d_in[16];
    const float* fcb1  = (const float*)d_in[17];
    const float* shW1  = (const float*)d_in[18];
    const float* shb1  = (const float*)d_in[19];
    const float* scW1  = (const float*)d_in[20];
    const float* scb1  = (const float*)d_in[21];
    const float* eps0  = (const float*)d_in[22];
    const float* eps1  = (const float*)d_in[23];

    const int n = N_NODES;
    float* out = (float*)d_out;
    float* theta0 = out;
    float* theta1 = theta0 + (size_t)128 * n;
    float* k0     = theta1 + (size_t)64  * n;
    float* k1     = k0     + (size_t)128 * n;
    float* l0     = k1     + (size_t)64  * n;
    float* l1     = l0     + (size_t)128 * n;

    float* xw0 = symaddrf(g_xw0);
    float* h0  = symaddrf(g_h0);
    float* xw1 = symaddrf(g_xw1);
    float* h1  = symaddrf(g_h1);
    float* z0  = symaddrf(g_z0);
    float* z1  = symaddrf(g_z1);
    float* s0  = symaddrf(g_s0);
    float* d0  = symaddrf(g_d0);
    float* s1  = symaddrf(g_s1);
    float* d1  = symaddrf(g_d1);
    float* wf01 = symaddrf(g_wf01);
    float* wkl0 = symaddrf(g_wkl0);
    float* wkl1 = symaddrf(g_wkl1);
    int* cnt = symaddri(g_cnt);
    int* cur = symaddri(g_cur);
    int* off = symaddri(g_off);
    int* csr = symaddri(g_csr);

    const int EB = (ET + 255) / 256;
    const int GX = (n + 127) / 128;       // 157 row tiles

    // ---- init + CSR build; xw0 GEMM at launch index 3 (profiled) ----
    init_kernel<<<(4 * n + 255) / 256, 256>>>(cnt, s0, d0, s1, d1);                   // 0
    hist_kernel<<<EB, 256>>>(ei, cnt);                                                // 1
    scan_kernel<<<1, 1024>>>(cnt, off, cur);                                          // 2
    gemm_mma_kernel<<<dim3(GX, 4), 256>>>(x, gatW0, n, 256, 1 << 30,
                                          xw0, nullptr, 4, 256,
                                          nullptr, nullptr, 0, 0,
                                          asrc0, adst0, s0, d0, 64);                   // 3 (profiled)
    scatter_kernel<<<EB, 256>>>(ei, off, cur, csr);                                   // 4

    // ---- weight concats (single launch) ----
    concat_kernel<<<128, 256>>>(wf01, wkl0, wkl1, gatW1, fcW0, shW0, scW0, shW1, scW1);

    // ---- layer 0 GAT ----
    gat_kernel<64><<<n, 256>>>(csr, off, s0, d0, xw0, gatb0, h0);

    // ---- fused xw1 (mode 4 -> s1/d1) + z0 (both consume h0, K=256, Ntot=256) ----
    gemm_mma_kernel<<<dim3(GX, 4), 256>>>(h0, wf01, n, 256, 128,
                                          xw1, nullptr, 4, 128,
                                          z0, fcb0, 1, 128,
                                          asrc1, adst1, s1, d1, 32);

    // ---- layer 1 GAT ----
    gat_kernel<32><<<n, 128>>>(csr, off, s1, d1, xw1, gatb1, h1);

    // ---- z1 (K=128, Ntot=64) ----
    gemm_mma_kernel<<<dim3(GX, 1), 256>>>(h1, fcW1, n, 128, 1 << 30,
                                          z1, fcb1, 1, 64,
                                          nullptr, nullptr, 0, 0,
                                          nullptr, nullptr, nullptr, nullptr, 1);

    // ---- fused k0 + l0 (K=128, Ntot=256, transposed stores) ----
    gemm_mma_kernel<<<dim3(GX, 4), 256>>>(z0, wkl0, n, 128, 128,
                                          k0, shb0, 2, n,
                                          l0, scb0, 3, n,
                                          nullptr, nullptr, nullptr, nullptr, 1);

    // ---- fused k1 + l1 (K=64, Ntot=128, transposed stores) ----
    gemm_mma_kernel<<<dim3(GX, 2), 256>>>(z1, wkl1, n, 64, 64,
                                          k1, shb1, 2, n,
                                          l1, scb1, 3, n,
                                          nullptr, nullptr, nullptr, nullptr, 1);

    // ---- fused kl_fix + theta ----
    theta_kernel<<<(128 * n + 255) / 256, 256>>>(k0, l0, eps0, theta0, 128 * n);
    theta_kernel<<<(64  * n + 255) / 256, 256>>>(k1, l1, eps1, theta1, 64 * n);
}

// round 11
// speedup vs baseline: 1.6549x; 1.1387x over previous
#include <cuda_runtime.h>
#include <math.h>
#include <stdint.h>

#define N_NODES 20000
#define NE      320000
#define ET      (NE + N_NODES)
#define HEADS   4

// ---------------- scratch (device globals; no allocation) ----------------
static __device__ float g_xw0[(size_t)N_NODES * 256];
static __device__ float g_h0 [(size_t)N_NODES * 256];
static __device__ float g_xw1[(size_t)N_NODES * 128];
static __device__ float g_h1 [(size_t)N_NODES * 128];
static __device__ float g_z0 [(size_t)N_NODES * 128];
static __device__ float g_z1 [(size_t)N_NODES * 64];
static __device__ float g_s0 [N_NODES * 4];
static __device__ float g_d0 [N_NODES * 4];
static __device__ float g_s1 [N_NODES * 4];
static __device__ float g_d1 [N_NODES * 4];
static __device__ int   g_cnt[N_NODES];
static __device__ int   g_cur[N_NODES];
static __device__ int   g_off[N_NODES + 1];
static __device__ int   g_csr[ET];
static __device__ float g_wf01[256 * 256];   // [gatW1 ; fcW0]
static __device__ float g_wkl0[256 * 128];   // [shW0 ; scW0]
static __device__ float g_wkl1[128 * 64];    // [shW1 ; scW1]

// ---------------- helpers ----------------
__device__ __forceinline__ float softplusf(float x) {
    return x > 20.f ? x : log1pf(__expf(x));
}
__device__ __forceinline__ void edge_uv(const int* __restrict__ ei, int e, int& u, int& v) {
    if (e < NE) { u = ei[e]; v = ei[NE + e]; }
    else        { u = v = e - NE; }   // self loops appended
}
__device__ __forceinline__ float tf32_round(float x) {
    uint32_t u;
    asm("cvt.rna.tf32.f32 %0, %1;" : "=r"(u) : "f"(x));
    return __uint_as_float(u);
}
__device__ __forceinline__ void mma8(float* c, const float* a, const float* b) {
    asm volatile(
        "mma.sync.aligned.m16n8k8.row.col.f32.tf32.tf32.f32 "
        "{%0,%1,%2,%3}, {%4,%5,%6,%7}, {%8,%9}, {%0,%1,%2,%3};"
        : "+f"(c[0]), "+f"(c[1]), "+f"(c[2]), "+f"(c[3])
        : "r"(__float_as_uint(a[0])), "r"(__float_as_uint(a[1])),
          "r"(__float_as_uint(a[2])), "r"(__float_as_uint(a[3])),
          "r"(__float_as_uint(b[0])), "r"(__float_as_uint(b[1])));
}

// ---------------- fused init: zero cnt + all 4 s/d buffers ----------------
__global__ void init_kernel(int* __restrict__ cnt, float* __restrict__ s0,
                            float* __restrict__ d0, float* __restrict__ s1,
                            float* __restrict__ d1) {
    int i = blockIdx.x * blockDim.x + threadIdx.x;
    if (i < N_NODES) cnt[i] = 0;
    if (i < N_NODES * 4) { s0[i] = 0.f; d0[i] = 0.f; s1[i] = 0.f; d1[i] = 0.f; }
}

// ---------------- fused weight concat (one launch) ----------------
__global__ void concat_kernel(float* __restrict__ wf01, float* __restrict__ wkl0,
                              float* __restrict__ wkl1,
                              const float* __restrict__ gatW1, const float* __restrict__ fcW0,
                              const float* __restrict__ shW0, const float* __restrict__ scW0,
                              const float* __restrict__ shW1, const float* __restrict__ scW1) {
    int i = blockIdx.x * blockDim.x + threadIdx.x;
    if (i < 32768) { wf01[i] = gatW1[i]; wf01[32768 + i] = fcW0[i]; }
    if (i < 16384) { wkl0[i] = shW0[i]; wkl0[16384 + i] = scW0[i]; }
    if (i < 4096)  { wkl1[i] = shW1[i]; wkl1[4096 + i] = scW1[i]; }
}

// ================= CSR build (group edges by dst) =================
__global__ void hist_kernel(const int* __restrict__ ei, int* __restrict__ cnt) {
    int e = blockIdx.x * blockDim.x + threadIdx.x;
    if (e >= ET) return;
    int u, v; edge_uv(ei, e, u, v);
    (void)u;
    atomicAdd(&cnt[v], 1);
}

__global__ void scan_kernel(const int* __restrict__ cnt, int* __restrict__ off,
                            int* __restrict__ cur) {
    const int CHUNK = (N_NODES + 1023) / 1024;   // 20
    __shared__ int ts[1024];
    int tid = threadIdx.x;
    int base = tid * CHUNK;
    int s = 0;
    for (int i = 0; i < CHUNK; i++) {
        int idx = base + i;
        if (idx < N_NODES) s += cnt[idx];
    }
    ts[tid] = s;
    __syncthreads();
    for (int o = 1; o < 1024; o <<= 1) {
        int v = (tid >= o) ? ts[tid - o] : 0;
        __syncthreads();
        ts[tid] += v;
        __syncthreads();
    }
    int run = (tid > 0) ? ts[tid - 1] : 0;
    for (int i = 0; i < CHUNK; i++) {
        int idx = base + i;
        if (idx < N_NODES) {
            off[idx] = run;
            run += cnt[idx];
            cur[idx] = 0;
        }
    }
    if (tid == (N_NODES - 1) / CHUNK) off[N_NODES] = run;
}

__global__ void scatter_kernel(const int* __restrict__ ei, const int* __restrict__ off,
                               int* __restrict__ cur, int* __restrict__ csr) {
    int e = blockIdx.x * blockDim.x + threadIdx.x;
    if (e >= ET) return;
    int u, v; edge_uv(ei, e, u, v);
    int pos = off[v] + atomicAdd(&cur[v], 1);
    csr[pos] = u;
}

// ================= 3xTF32 mma.sync GEMM (BK=32, raw f32 smem, register split) ======
// C[n, Ntot] = A[n,K] * W[Ntot,K]^T; CTA tile 128 x 64, 8 warps (4 M x 2 N),
// warp tile 32 x 32. D = Ahi*Bhi + Ahi*Blo + Alo*Bhi (~fp32 accuracy).
// mode: 0 plain rowmajor, 1 softplus rowmajor, 2 softplus+clip transposed,
//       3 softplus transposed, 4 plain rowmajor + GAT s/d accumulation (atomicAdd).
__global__ void __launch_bounds__(256, 2)
gemm_mma_kernel(const float* __restrict__ A, const float* __restrict__ W,
                int n, int K, int nsplit,
                float* __restrict__ outA, const float* __restrict__ biasA, int modeA, int strideA,
                float* __restrict__ outB, const float* __restrict__ biasB, int modeB, int strideB,
                const float* __restrict__ asrcP, const float* __restrict__ adstP,
                float* __restrict__ sOut, float* __restrict__ dOut, int headC) {
    constexpr int BM = 128, BN = 64, BK = 32;
    constexpr int KP = 36;                     // padded row stride (floats); 4*gr+tig walks banks
    constexpr int NT = 4;                      // n-tiles (8 cols) per warp (32 cols)
    constexpr int AF4 = BM * BK / 4 / 256;     // 4
    constexpr int BF4 = BN * BK / 4 / 256;     // 2

    __shared__ __align__(16) float As[BM * KP];
    __shared__ __align__(16) float Bs[BN * KP];

    const int tid = threadIdx.x;
    const int wid = tid >> 5, lane = tid & 31;
    const int gr = lane >> 2, tig = lane & 3;
    const int warpM = (wid & 3) * 32;
    const int warpN = (wid >> 2) * 32;
    const int bi = blockIdx.x * BM;
    const int bj = blockIdx.y * BN;

    float acc[2][NT][4];
#pragma unroll
    for (int mt = 0; mt < 2; mt++)
#pragma unroll
        for (int nt = 0; nt < NT; nt++)
#pragma unroll
            for (int q = 0; q < 4; q++) acc[mt][nt][q] = 0.f;

    const int nchunk = K / BK;

    int arows[AF4], aqs[AF4]; bool avs[AF4];
#pragma unroll
    for (int i = 0; i < AF4; i++) {
        int idx = tid + i * 256;
        arows[i] = idx >> 3; aqs[i] = idx & 7;
        avs[i] = (bi + arows[i]) < n;
    }
    int brows[BF4], bqs[BF4];
#pragma unroll
    for (int i = 0; i < BF4; i++) {
        int idx = tid + i * 256;
        brows[i] = idx >> 3; bqs[i] = idx & 7;
    }

    float4 apre[AF4], bpre[BF4];
#pragma unroll
    for (int i = 0; i < AF4; i++)
        apre[i] = avs[i] ? *(const float4*)(A + (size_t)(bi + arows[i]) * K + aqs[i] * 4)
                         : make_float4(0.f, 0.f, 0.f, 0.f);
#pragma unroll
    for (int i = 0; i < BF4; i++)
        bpre[i] = *(const float4*)(W + (size_t)(bj + brows[i]) * K + bqs[i] * 4);

    for (int c = 0; c < nchunk; c++) {
#pragma unroll
        for (int i = 0; i < AF4; i++)
            *(float4*)&As[arows[i] * KP + aqs[i] * 4] = apre[i];
#pragma unroll
        for (int i = 0; i < BF4; i++)
            *(float4*)&Bs[brows[i] * KP + bqs[i] * 4] = bpre[i];
        __syncthreads();

        if (c + 1 < nchunk) {
            int k0 = (c + 1) * BK;
#pragma unroll
            for (int i = 0; i < AF4; i++)
                apre[i] = avs[i] ? *(const float4*)(A + (size_t)(bi + arows[i]) * K + k0 + aqs[i] * 4)
                                 : make_float4(0.f, 0.f, 0.f, 0.f);
#pragma unroll
            for (int i = 0; i < BF4; i++)
                bpre[i] = *(const float4*)(W + (size_t)(bj + brows[i]) * K + k0 + bqs[i] * 4);
        }

#pragma unroll
        for (int kb = 0; kb < BK; kb += 8) {
            float ah[2][4], al[2][4];
#pragma unroll
            for (int mt = 0; mt < 2; mt++) {
                int r0 = (warpM + mt * 16 + gr) * KP + kb + tig;
                int r1 = r0 + 8 * KP;
                float raw0 = As[r0], raw1 = As[r1], raw2 = As[r0 + 4], raw3 = As[r1 + 4];
                ah[mt][0] = tf32_round(raw0); al[mt][0] = raw0 - ah[mt][0];
                ah[mt][1] = tf32_round(raw1); al[mt][1] = raw1 - ah[mt][1];
                ah[mt][2] = tf32_round(raw2); al[mt][2] = raw2 - ah[mt][2];
                ah[mt][3] = tf32_round(raw3); al[mt][3] = raw3 - ah[mt][3];
            }
#pragma unroll
            for (int nt = 0; nt < NT; nt++) {
                int b0 = (warpN + nt * 8 + gr) * KP + kb + tig;
                float braw0 = Bs[b0], braw1 = Bs[b0 + 4];
                float bh[2], bl[2];
                bh[0] = tf32_round(braw0); bl[0] = braw0 - bh[0];
                bh[1] = tf32_round(braw1); bl[1] = braw1 - bh[1];
#pragma unroll
                for (int mt = 0; mt < 2; mt++) {
                    mma8(acc[mt][nt], ah[mt], bh);
                    mma8(acc[mt][nt], ah[mt], bl);
                    mma8(acc[mt][nt], al[mt], bh);
                }
            }
        }
        __syncthreads();
    }

    // ---- epilogue (segment uniform per warp: nsplit is a multiple of 32) ----
    const int jbase = bj + warpN;
    float* o; const float* bp; int mode, stride, joff;
    if (jbase < nsplit) { o = outA; bp = biasA; mode = modeA; stride = strideA; joff = 0; }
    else                { o = outB; bp = biasB; mode = modeB; stride = strideB; joff = nsplit; }

#pragma unroll
    for (int mt = 0; mt < 2; mt++) {
#pragma unroll
        for (int half = 0; half < 2; half++) {
            int row = bi + warpM + mt * 16 + gr + half * 8;
            if (row >= n) continue;
            float ss = 0.f, dd = 0.f;
#pragma unroll
            for (int nt = 0; nt < NT; nt++) {
#pragma unroll
                for (int p = 0; p < 2; p++) {
                    int jj = jbase + nt * 8 + 2 * tig + p;
                    float v = acc[mt][nt][half * 2 + p];
                    int j = jj - joff;
                    if (mode == 4) {
                        o[(size_t)row * stride + j] = v;
                        ss += v * asrcP[jj];
                        dd += v * adstP[jj];
                    } else {
                        v += bp ? bp[j] : 0.f;
                        if (mode != 0) v = softplusf(v);
                        if (mode == 2) v = fminf(fmaxf(v, 0.1f), 1000.f);
                        if (mode >= 2) o[(size_t)j * stride + row] = v;
                        else           o[(size_t)row * stride + j] = v;
                    }
                }
            }
            if (mode == 4) {
                int h = jbase / headC;       // warp tile lies in exactly one head
                atomicAdd(&sOut[row * 4 + h], ss);
                atomicAdd(&dOut[row * 4 + h], dd);
            }
        }
    }
}

// ================= fused per-node GAT softmax + aggregation =================
template <int C>
__global__ void gat_kernel(const int* __restrict__ csr, const int* __restrict__ off,
                           const float* __restrict__ s, const float* __restrict__ d,
                           const float* __restrict__ xw, const float* __restrict__ bias,
                           float* __restrict__ out) {
    constexpr int HC = 4 * C;
    const int v = blockIdx.x;
    const int tid = threadIdx.x;
    const int h = tid / C;
    const int c = tid - h * C;           // in-head lane 0..C-1
    const int beg = off[v], end = off[v + 1];

    __shared__ float red[HC];
    __shared__ float mh[4], inv[4];

    const float dv = d[v * 4 + h];

    float lmax = -INFINITY;
    for (int j = beg + c; j < end; j += C) {
        int u = csr[j];
        float e = s[u * 4 + h] + dv;
        e = e > 0.f ? e : 0.2f * e;
        lmax = fmaxf(lmax, e);
    }
    red[tid] = lmax;
    __syncthreads();
    if (tid < 4) {
        float m = -INFINITY;
        for (int i = 0; i < C; i++) m = fmaxf(m, red[tid * C + i]);
        mh[tid] = m;
    }
    __syncthreads();
    const float m = mh[h];

    float lsum = 0.f;
    for (int j = beg + c; j < end; j += C) {
        int u = csr[j];
        float e = s[u * 4 + h] + dv;
        e = e > 0.f ? e : 0.2f * e;
        lsum += __expf(e - m);
    }
    red[tid] = lsum;
    __syncthreads();
    if (tid < 4) {
        float sm = 0.f;
        for (int i = 0; i < C; i++) sm += red[tid * C + i];
        inv[tid] = 1.f / (sm + 1e-16f);
    }
    __syncthreads();
    const float invden = inv[h];

    float acc = 0.f;
    for (int j = beg; j < end; j++) {
        int u = csr[j];
        float e = s[u * 4 + h] + dv;
        e = e > 0.f ? e : 0.2f * e;
        float w = __expf(e - m) * invden;
        acc = fmaf(w, xw[(size_t)u * HC + tid], acc);
    }
    out[(size_t)v * HC + tid] = acc + bias[tid];
}

// ---------------- fused kl_fix + theta ----------------
__global__ void theta_kernel(const float* __restrict__ k, float* __restrict__ l,
                             const float* __restrict__ eps, float* __restrict__ th, int ZN) {
    int i = blockIdx.x * blockDim.x + threadIdx.x;
    if (i >= ZN) return;
    float kk = k[i];
    float invk = 1.f / kk;
    float ll = fmaxf(l[i], 2.2e-10f) * expf(-lgammaf(1.f + invk));
    l[i] = ll;
    float acc = 0.f;
#pragma unroll
    for (int s = 0; s < 10; s++) {
        float ep = eps[(size_t)s * ZN + i];
        float t = fmaxf(1.f - ep, 2.2e-10f);
        float nl = -__logf(t);
        acc += __powf(nl, invk);
    }
    float theta = ll * acc * 0.1f;
    th[i] = fminf(fmaxf(theta, 2.2e-10f), 1000.f);
}

// ---------------- host launch ----------------
template <typename T>
static float* symaddrf(T& sym) { void* p = nullptr; cudaGetSymbolAddress(&p, sym); return (float*)p; }
template <typename T>
static int* symaddri(T& sym) { void* p = nullptr; cudaGetSymbolAddress(&p, sym); return (int*)p; }

// stream/event handles: created once (host objects, not device memory)
static cudaStream_t g_s2 = nullptr;
static cudaEvent_t g_evA, g_evCSR, g_evZ0, g_evT0;

extern "C" void kernel_launch(void* const* d_in, const int* in_sizes, int n_in,
                              void* d_out, int out_size) {
    if (!g_s2) {
        cudaStreamCreateWithFlags(&g_s2, cudaStreamNonBlocking);
        cudaEventCreateWithFlags(&g_evA,   cudaEventDisableTiming);
        cudaEventCreateWithFlags(&g_evCSR, cudaEventDisableTiming);
        cudaEventCreateWithFlags(&g_evZ0,  cudaEventDisableTiming);
        cudaEventCreateWithFlags(&g_evT0,  cudaEventDisableTiming);
    }

    const float* x     = (const float*)d_in[0];
    const int*   ei    = (const int*)  d_in[1];
    const float* gatW0 = (const float*)d_in[2];
    const float* asrc0 = (const float*)d_in[3];
    const float* adst0 = (const float*)d_in[4];
    const float* gatb0 = (const float*)d_in[5];
    const float* fcW0  = (const float*)d_in[6];
    const float* fcb0  = (const float*)d_in[7];
    const float* shW0  = (const float*)d_in[8];
    const float* shb0  = (const float*)d_in[9];
    const float* scW0  = (const float*)d_in[10];
    const float* scb0  = (const float*)d_in[11];
    const float* gatW1 = (const float*)d_in[12];
    const float* asrc1 = (const float*)d_in[13];
    const float* adst1 = (const float*)d_in[14];
    const float* gatb1 = (const float*)d_in[15];
    const float* fcW1  = (const float*)d_in[16];
    const float* fcb1  = (const float*)d_in[17];
    const float* shW1  = (const float*)d_in[18];
    const float* shb1  = (const float*)d_in[19];
    const float* scW1  = (const float*)d_in[20];
    const float* scb1  = (const float*)d_in[21];
    const float* eps0  = (const float*)d_in[22];
    const float* eps1  = (const float*)d_in[23];

    const int n = N_NODES;
    float* out = (float*)d_out;
    float* theta0 = out;
    float* theta1 = theta0 + (size_t)128 * n;
    float* k0     = theta1 + (size_t)64  * n;
    float* k1     = k0     + (size_t)128 * n;
    float* l0     = k1     + (size_t)64  * n;
    float* l1     = l0     + (size_t)128 * n;

    float* xw0 = symaddrf(g_xw0);
    float* h0  = symaddrf(g_h0);
    float* xw1 = symaddrf(g_xw1);
    float* h1  = symaddrf(g_h1);
    float* z0  = symaddrf(g_z0);
    float* z1  = symaddrf(g_z1);
    float* s0  = symaddrf(g_s0);
    float* d0  = symaddrf(g_d0);
    float* s1  = symaddrf(g_s1);
    float* d1  = symaddrf(g_d1);
    float* wf01 = symaddrf(g_wf01);
    float* wkl0 = symaddrf(g_wkl0);
    float* wkl1 = symaddrf(g_wkl1);
    int* cnt = symaddri(g_cnt);
    int* cur = symaddri(g_cur);
    int* off = symaddri(g_off);
    int* csr = symaddri(g_csr);

    const int EB = (ET + 255) / 256;
    const int GX = (n + 127) / 128;       // 157 row tiles

    // ===== default stream (d): init, then fork CSR build to s2 =====
    init_kernel<<<(4 * n + 255) / 256, 256>>>(cnt, s0, d0, s1, d1);
    cudaEventRecord(g_evA, 0);
    cudaStreamWaitEvent(g_s2, g_evA, 0);

    // ---- s2: CSR build (overlaps with xw0 GEMM on d) ----
    hist_kernel<<<EB, 256, 0, g_s2>>>(ei, cnt);
    scan_kernel<<<1, 1024, 0, g_s2>>>(cnt, off, cur);
    scatter_kernel<<<EB, 256, 0, g_s2>>>(ei, off, cur, csr);
    cudaEventRecord(g_evCSR, g_s2);

    // ---- d: weight concat + xw0 GEMM (mode 4 -> xw0, s0, d0) ----
    concat_kernel<<<128, 256>>>(wf01, wkl0, wkl1, gatW1, fcW0, shW0, scW0, shW1, scW1);
    gemm_mma_kernel<<<dim3(GX, 4), 256>>>(x, gatW0, n, 256, 1 << 30,
                                          xw0, nullptr, 4, 256,
                                          nullptr, nullptr, 0, 0,
                                          asrc0, adst0, s0, d0, 64);

    // ---- d: join CSR, then layer-0 GAT + fused xw1/z0 GEMM ----
    cudaStreamWaitEvent(0, g_evCSR, 0);
    gat_kernel<64><<<n, 256>>>(csr, off, s0, d0, xw0, gatb0, h0);
    gemm_mma_kernel<<<dim3(GX, 4), 256>>>(h0, wf01, n, 256, 128,
                                          xw1, nullptr, 4, 128,
                                          z0, fcb0, 1, 128,
                                          asrc1, adst1, s1, d1, 32);
    cudaEventRecord(g_evZ0, 0);

    // ---- s2: layer-0 head chain (kl0 -> theta0), overlaps with layer-1 chain on d ----
    cudaStreamWaitEvent(g_s2, g_evZ0, 0);
    gemm_mma_kernel<<<dim3(GX, 4), 256, 0, g_s2>>>(z0, wkl0, n, 128, 128,
                                                   k0, shb0, 2, n,
                                                   l0, scb0, 3, n,
                                                   nullptr, nullptr, nullptr, nullptr, 1);
    theta_kernel<<<(128 * n + 255) / 256, 256, 0, g_s2>>>(k0, l0, eps0, theta0, 128 * n);
    cudaEventRecord(g_evT0, g_s2);

    // ---- d: layer-1 chain (gat1 -> z1 -> kl1 -> theta1) ----
    gat_kernel<32><<<n, 128>>>(csr, off, s1, d1, xw1, gatb1, h1);
    gemm_mma_kernel<<<dim3(GX, 1), 256>>>(h1, fcW1, n, 128, 1 << 30,
                                          z1, fcb1, 1, 64,
                                          nullptr, nullptr, 0, 0,
                                          nullptr, nullptr, nullptr, nullptr, 1);
    gemm_mma_kernel<<<dim3(GX, 2), 256>>>(z1, wkl1, n, 64, 64,
                                          k1, shb1, 2, n,
                                          l1, scb1, 3, n,
                                          nullptr, nullptr, nullptr, nullptr, 1);
    theta_kernel<<<(64 * n + 255) / 256, 256>>>(k1, l1, eps1, theta1, 64 * n);

    // ---- join s2 back into d before return ----
    cudaStreamWaitEvent(0, g_evT0, 0);
}

// round 12
// speedup vs baseline: 1.6648x; 1.0060x over previous
#include <cuda_runtime.h>
#include <math.h>
#include <stdint.h>

#define N_NODES 20000
#define NE      320000
#define ET      (NE + N_NODES)
#define HEADS   4

// ---------------- scratch (device globals; no allocation) ----------------
static __device__ float g_xw0[(size_t)N_NODES * 256];
static __device__ float g_h0 [(size_t)N_NODES * 256];
static __device__ float g_xw1[(size_t)N_NODES * 128];
static __device__ float g_h1 [(size_t)N_NODES * 128];
static __device__ float g_z0 [(size_t)N_NODES * 128];
static __device__ float g_z1 [(size_t)N_NODES * 64];
static __device__ float g_s0 [N_NODES * 4];
static __device__ float g_d0 [N_NODES * 4];
static __device__ float g_s1 [N_NODES * 4];
static __device__ float g_d1 [N_NODES * 4];
static __device__ int   g_cnt[N_NODES];
static __device__ int   g_cur[N_NODES];
static __device__ int   g_off[N_NODES + 1];
static __device__ int   g_csr[ET];
static __device__ float g_wf01[256 * 256];   // [gatW1 ; fcW0]
static __device__ float g_wkl0[256 * 128];   // [shW0 ; scW0]
static __device__ float g_wkl1[128 * 64];    // [shW1 ; scW1]

// ---------------- helpers ----------------
__device__ __forceinline__ float softplusf(float x) {
    return x > 20.f ? x : log1pf(__expf(x));
}
__device__ __forceinline__ void edge_uv(const int* __restrict__ ei, int e, int& u, int& v) {
    if (e < NE) { u = ei[e]; v = ei[NE + e]; }
    else        { u = v = e - NE; }   // self loops appended
}
__device__ __forceinline__ float tf32_round(float x) {
    uint32_t u;
    asm("cvt.rna.tf32.f32 %0, %1;" : "=r"(u) : "f"(x));
    return __uint_as_float(u);
}
__device__ __forceinline__ void mma8(float* c, const float* a, const float* b) {
    asm volatile(
        "mma.sync.aligned.m16n8k8.row.col.f32.tf32.tf32.f32 "
        "{%0,%1,%2,%3}, {%4,%5,%6,%7}, {%8,%9}, {%0,%1,%2,%3};"
        : "+f"(c[0]), "+f"(c[1]), "+f"(c[2]), "+f"(c[3])
        : "r"(__float_as_uint(a[0])), "r"(__float_as_uint(a[1])),
          "r"(__float_as_uint(a[2])), "r"(__float_as_uint(a[3])),
          "r"(__float_as_uint(b[0])), "r"(__float_as_uint(b[1])));
}

// ---------------- fused init: zero cnt + all 4 s/d buffers ----------------
__global__ void init_kernel(int* __restrict__ cnt, float* __restrict__ s0,
                            float* __restrict__ d0, float* __restrict__ s1,
                            float* __restrict__ d1) {
    int i = blockIdx.x * blockDim.x + threadIdx.x;
    if (i < N_NODES) cnt[i] = 0;
    if (i < N_NODES * 4) { s0[i] = 0.f; d0[i] = 0.f; s1[i] = 0.f; d1[i] = 0.f; }
}

// ---------------- fused weight concat (one launch) ----------------
__global__ void concat_kernel(float* __restrict__ wf01, float* __restrict__ wkl0,
                              float* __restrict__ wkl1,
                              const float* __restrict__ gatW1, const float* __restrict__ fcW0,
                              const float* __restrict__ shW0, const float* __restrict__ scW0,
                              const float* __restrict__ shW1, const float* __restrict__ scW1) {
    int i = blockIdx.x * blockDim.x + threadIdx.x;
    if (i < 32768) { wf01[i] = gatW1[i]; wf01[32768 + i] = fcW0[i]; }
    if (i < 16384) { wkl0[i] = shW0[i]; wkl0[16384 + i] = scW0[i]; }
    if (i < 4096)  { wkl1[i] = shW1[i]; wkl1[4096 + i] = scW1[i]; }
}

// ================= CSR build (group edges by dst) =================
__global__ void hist_kernel(const int* __restrict__ ei, int* __restrict__ cnt) {
    int e = blockIdx.x * blockDim.x + threadIdx.x;
    if (e >= ET) return;
    int u, v; edge_uv(ei, e, u, v);
    (void)u;
    atomicAdd(&cnt[v], 1);
}

__global__ void scan_kernel(const int* __restrict__ cnt, int* __restrict__ off,
                            int* __restrict__ cur) {
    const int CHUNK = (N_NODES + 1023) / 1024;   // 20
    __shared__ int ts[1024];
    int tid = threadIdx.x;
    int base = tid * CHUNK;
    int s = 0;
    for (int i = 0; i < CHUNK; i++) {
        int idx = base + i;
        if (idx < N_NODES) s += cnt[idx];
    }
    ts[tid] = s;
    __syncthreads();
    for (int o = 1; o < 1024; o <<= 1) {
        int v = (tid >= o) ? ts[tid - o] : 0;
        __syncthreads();
        ts[tid] += v;
        __syncthreads();
    }
    int run = (tid > 0) ? ts[tid - 1] : 0;
    for (int i = 0; i < CHUNK; i++) {
        int idx = base + i;
        if (idx < N_NODES) {
            off[idx] = run;
            run += cnt[idx];
            cur[idx] = 0;
        }
    }
    if (tid == (N_NODES - 1) / CHUNK) off[N_NODES] = run;
}

__global__ void scatter_kernel(const int* __restrict__ ei, const int* __restrict__ off,
                               int* __restrict__ cur, int* __restrict__ csr) {
    int e = blockIdx.x * blockDim.x + threadIdx.x;
    if (e >= ET) return;
    int u, v; edge_uv(ei, e, u, v);
    int pos = off[v] + atomicAdd(&cur[v], 1);
    csr[pos] = u;
}

// ================= 3xTF32 mma.sync GEMM (BK=32, raw f32 smem, register split) ======
// mode: 0 plain rowmajor, 1 softplus rowmajor, 2 softplus+clip transposed,
//       3 softplus transposed, 4 plain rowmajor + GAT s/d accumulation (atomicAdd).
__global__ void __launch_bounds__(256, 2)
gemm_mma_kernel(const float* __restrict__ A, const float* __restrict__ W,
                int n, int K, int nsplit,
                float* __restrict__ outA, const float* __restrict__ biasA, int modeA, int strideA,
                float* __restrict__ outB, const float* __restrict__ biasB, int modeB, int strideB,
                const float* __restrict__ asrcP, const float* __restrict__ adstP,
                float* __restrict__ sOut, float* __restrict__ dOut, int headC) {
    constexpr int BM = 128, BN = 64, BK = 32;
    constexpr int KP = 36;
    constexpr int NT = 4;
    constexpr int AF4 = BM * BK / 4 / 256;     // 4
    constexpr int BF4 = BN * BK / 4 / 256;     // 2

    __shared__ __align__(16) float As[BM * KP];
    __shared__ __align__(16) float Bs[BN * KP];

    const int tid = threadIdx.x;
    const int wid = tid >> 5, lane = tid & 31;
    const int gr = lane >> 2, tig = lane & 3;
    const int warpM = (wid & 3) * 32;
    const int warpN = (wid >> 2) * 32;
    const int bi = blockIdx.x * BM;
    const int bj = blockIdx.y * BN;

    float acc[2][NT][4];
#pragma unroll
    for (int mt = 0; mt < 2; mt++)
#pragma unroll
        for (int nt = 0; nt < NT; nt++)
#pragma unroll
            for (int q = 0; q < 4; q++) acc[mt][nt][q] = 0.f;

    const int nchunk = K / BK;

    int arows[AF4], aqs[AF4]; bool avs[AF4];
#pragma unroll
    for (int i = 0; i < AF4; i++) {
        int idx = tid + i * 256;
        arows[i] = idx >> 3; aqs[i] = idx & 7;
        avs[i] = (bi + arows[i]) < n;
    }
    int brows[BF4], bqs[BF4];
#pragma unroll
    for (int i = 0; i < BF4; i++) {
        int idx = tid + i * 256;
        brows[i] = idx >> 3; bqs[i] = idx & 7;
    }

    float4 apre[AF4], bpre[BF4];
#pragma unroll
    for (int i = 0; i < AF4; i++)
        apre[i] = avs[i] ? *(const float4*)(A + (size_t)(bi + arows[i]) * K + aqs[i] * 4)
                         : make_float4(0.f, 0.f, 0.f, 0.f);
#pragma unroll
    for (int i = 0; i < BF4; i++)
        bpre[i] = *(const float4*)(W + (size_t)(bj + brows[i]) * K + bqs[i] * 4);

    for (int c = 0; c < nchunk; c++) {
#pragma unroll
        for (int i = 0; i < AF4; i++)
            *(float4*)&As[arows[i] * KP + aqs[i] * 4] = apre[i];
#pragma unroll
        for (int i = 0; i < BF4; i++)
            *(float4*)&Bs[brows[i] * KP + bqs[i] * 4] = bpre[i];
        __syncthreads();

        if (c + 1 < nchunk) {
            int k0 = (c + 1) * BK;
#pragma unroll
            for (int i = 0; i < AF4; i++)
                apre[i] = avs[i] ? *(const float4*)(A + (size_t)(bi + arows[i]) * K + k0 + aqs[i] * 4)
                                 : make_float4(0.f, 0.f, 0.f, 0.f);
#pragma unroll
            for (int i = 0; i < BF4; i++)
                bpre[i] = *(const float4*)(W + (size_t)(bj + brows[i]) * K + k0 + bqs[i] * 4);
        }

#pragma unroll
        for (int kb = 0; kb < BK; kb += 8) {
            float ah[2][4], al[2][4];
#pragma unroll
            for (int mt = 0; mt < 2; mt++) {
                int r0 = (warpM + mt * 16 + gr) * KP + kb + tig;
                int r1 = r0 + 8 * KP;
                float raw0 = As[r0], raw1 = As[r1], raw2 = As[r0 + 4], raw3 = As[r1 + 4];
                ah[mt][0] = tf32_round(raw0); al[mt][0] = raw0 - ah[mt][0];
                ah[mt][1] = tf32_round(raw1); al[mt][1] = raw1 - ah[mt][1];
                ah[mt][2] = tf32_round(raw2); al[mt][2] = raw2 - ah[mt][2];
                ah[mt][3] = tf32_round(raw3); al[mt][3] = raw3 - ah[mt][3];
            }
#pragma unroll
            for (int nt = 0; nt < NT; nt++) {
                int b0 = (warpN + nt * 8 + gr) * KP + kb + tig;
                float braw0 = Bs[b0], braw1 = Bs[b0 + 4];
                float bh[2], bl[2];
                bh[0] = tf32_round(braw0); bl[0] = braw0 - bh[0];
                bh[1] = tf32_round(braw1); bl[1] = braw1 - bh[1];
#pragma unroll
                for (int mt = 0; mt < 2; mt++) {
                    mma8(acc[mt][nt], ah[mt], bh);
                    mma8(acc[mt][nt], ah[mt], bl);
                    mma8(acc[mt][nt], al[mt], bh);
                }
            }
        }
        __syncthreads();
    }

    // ---- epilogue (segment uniform per warp: nsplit is a multiple of 32) ----
    const int jbase = bj + warpN;
    float* o; const float* bp; int mode, stride, joff;
    if (jbase < nsplit) { o = outA; bp = biasA; mode = modeA; stride = strideA; joff = 0; }
    else                { o = outB; bp = biasB; mode = modeB; stride = strideB; joff = nsplit; }

#pragma unroll
    for (int mt = 0; mt < 2; mt++) {
#pragma unroll
        for (int half = 0; half < 2; half++) {
            int row = bi + warpM + mt * 16 + gr + half * 8;
            if (row >= n) continue;
            float ss = 0.f, dd = 0.f;
#pragma unroll
            for (int nt = 0; nt < NT; nt++) {
#pragma unroll
                for (int p = 0; p < 2; p++) {
                    int jj = jbase + nt * 8 + 2 * tig + p;
                    float v = acc[mt][nt][half * 2 + p];
                    int j = jj - joff;
                    if (mode == 4) {
                        o[(size_t)row * stride + j] = v;
                        ss += v * asrcP[jj];
                        dd += v * adstP[jj];
                    } else {
                        v += bp ? bp[j] : 0.f;
                        if (mode != 0) v = softplusf(v);
                        if (mode == 2) v = fminf(fmaxf(v, 0.1f), 1000.f);
                        if (mode >= 2) o[(size_t)j * stride + row] = v;
                        else           o[(size_t)row * stride + j] = v;
                    }
                }
            }
            if (mode == 4) {
                int h = jbase / headC;
                atomicAdd(&sOut[row * 4 + h], ss);
                atomicAdd(&dOut[row * 4 + h], dd);
            }
        }
    }
}

// ================= fused per-node GAT v2: dedup exp via smem tiles =================
// blockDim = HC; pass 3 tiles edges: compute phase (TILE edges x 4 heads, one w each)
// then broadcast aggregation. Exp count per block: 8*deg instead of (HC+4)*deg.
template <int C>
__global__ void gat_kernel(const int* __restrict__ csr, const int* __restrict__ off,
                           const float* __restrict__ s, const float* __restrict__ d,
                           const float* __restrict__ xw, const float* __restrict__ bias,
                           float* __restrict__ out) {
    constexpr int HC = 4 * C;
    constexpr int TILE = HC / 4;         // 64 (C=64) or 32 (C=32)
    const int v = blockIdx.x;
    const int tid = threadIdx.x;
    const int h = tid / C;
    const int c = tid - h * C;
    const int beg = off[v], end = off[v + 1];

    __shared__ float red[HC];
    __shared__ float mh[4], inv[4];
    __shared__ float wsh[TILE * 4];
    __shared__ int   ush[TILE];

    const float dv = d[v * 4 + h];

    // pass 1: per-head max of leaky(s[u]+d[v]) — each head group covers all edges
    float lmax = -INFINITY;
    for (int j = beg + c; j < end; j += C) {
        int u = csr[j];
        float e = s[u * 4 + h] + dv;
        e = e > 0.f ? e : 0.2f * e;
        lmax = fmaxf(lmax, e);
    }
    red[tid] = lmax;
    __syncthreads();
    if (tid < 4) {
        float m = -INFINITY;
        for (int i = 0; i < C; i++) m = fmaxf(m, red[tid * C + i]);
        mh[tid] = m;
    }
    __syncthreads();
    const float m = mh[h];

    // pass 2: per-head sum of exp(e - m)
    float lsum = 0.f;
    for (int j = beg + c; j < end; j += C) {
        int u = csr[j];
        float e = s[u * 4 + h] + dv;
        e = e > 0.f ? e : 0.2f * e;
        lsum += __expf(e - m);
    }
    red[tid] = lsum;
    __syncthreads();
    if (tid < 4) {
        float sm = 0.f;
        for (int i = 0; i < C; i++) sm += red[tid * C + i];
        inv[tid] = 1.f / (sm + 1e-16f);
    }
    __syncthreads();

    // pass 3: tiled — compute w once per (edge, head), then broadcast aggregate
    float acc = 0.f;
    const int je = tid >> 2;             // 0..TILE-1
    const int hh = tid & 3;
    for (int t0 = beg; t0 < end; t0 += TILE) {
        int mc = end - t0; if (mc > TILE) mc = TILE;
        if (je < mc) {
            int u = csr[t0 + je];
            if (hh == 0) ush[je] = u;
            float e = s[u * 4 + hh] + d[v * 4 + hh];
            e = e > 0.f ? e : 0.2f * e;
            wsh[je * 4 + hh] = __expf(e - mh[hh]) * inv[hh];
        }
        __syncthreads();
        for (int q = 0; q < mc; q++)
            acc = fmaf(wsh[q * 4 + h], xw[(size_t)ush[q] * HC + tid], acc);
        __syncthreads();
    }
    out[(size_t)v * HC + tid] = acc + bias[tid];
}

// ---------------- fused kl_fix + theta ----------------
__global__ void theta_kernel(const float* __restrict__ k, float* __restrict__ l,
                             const float* __restrict__ eps, float* __restrict__ th, int ZN) {
    int i = blockIdx.x * blockDim.x + threadIdx.x;
    if (i >= ZN) return;
    float kk = k[i];
    float invk = 1.f / kk;
    float ll = fmaxf(l[i], 2.2e-10f) * expf(-lgammaf(1.f + invk));
    l[i] = ll;
    float acc = 0.f;
#pragma unroll
    for (int s = 0; s < 10; s++) {
        float ep = eps[(size_t)s * ZN + i];
        float t = fmaxf(1.f - ep, 2.2e-10f);
        float nl = -__logf(t);
        acc += __powf(nl, invk);
    }
    float theta = ll * acc * 0.1f;
    th[i] = fminf(fmaxf(theta, 2.2e-10f), 1000.f);
}

// ---------------- host launch ----------------
template <typename T>
static float* symaddrf(T& sym) { void* p = nullptr; cudaGetSymbolAddress(&p, sym); return (float*)p; }
template <typename T>
static int* symaddri(T& sym) { void* p = nullptr; cudaGetSymbolAddress(&p, sym); return (int*)p; }

static cudaStream_t g_s2 = nullptr;
static cudaEvent_t g_evA, g_evCSR, g_evZ0, g_evT0;

extern "C" void kernel_launch(void* const* d_in, const int* in_sizes, int n_in,
                              void* d_out, int out_size) {
    if (!g_s2) {
        cudaStreamCreateWithFlags(&g_s2, cudaStreamNonBlocking);
        cudaEventCreateWithFlags(&g_evA,   cudaEventDisableTiming);
        cudaEventCreateWithFlags(&g_evCSR, cudaEventDisableTiming);
        cudaEventCreateWithFlags(&g_evZ0,  cudaEventDisableTiming);
        cudaEventCreateWithFlags(&g_evT0,  cudaEventDisableTiming);
    }

    const float* x     = (const float*)d_in[0];
    const int*   ei    = (const int*)  d_in[1];
    const float* gatW0 = (const float*)d_in[2];
    const float* asrc0 = (const float*)d_in[3];
    const float* adst0 = (const float*)d_in[4];
    const float* gatb0 = (const float*)d_in[5];
    const float* fcW0  = (const float*)d_in[6];
    const float* fcb0  = (const float*)d_in[7];
    const float* shW0  = (const float*)d_in[8];
    const float* shb0  = (const float*)d_in[9];
    const float* scW0  = (const float*)d_in[10];
    const float* scb0  = (const float*)d_in[11];
    const float* gatW1 = (const float*)d_in[12];
    const float* asrc1 = (const float*)d_in[13];
    const float* adst1 = (const float*)d_in[14];
    const float* gatb1 = (const float*)d_in[15];
    const float* fcW1  = (const float*)d_in[16];
    const float* fcb1  = (const float*)d_in[17];
    const float* shW1  = (const float*)d_in[18];
    const float* shb1  = (const float*)d_in[19];
    const float* scW1  = (const float*)d_in[20];
    const float* scb1  = (const float*)d_in[21];
    const float* eps0  = (const float*)d_in[22];
    const float* eps1  = (const float*)d_in[23];

    const int n = N_NODES;
    float* out = (float*)d_out;
    float* theta0 = out;
    float* theta1 = theta0 + (size_t)128 * n;
    float* k0     = theta1 + (size_t)64  * n;
    float* k1     = k0     + (size_t)128 * n;
    float* l0     = k1     + (size_t)64  * n;
    float* l1     = l0     + (size_t)128 * n;

    float* xw0 = symaddrf(g_xw0);
    float* h0  = symaddrf(g_h0);
    float* xw1 = symaddrf(g_xw1);
    float* h1  = symaddrf(g_h1);
    float* z0  = symaddrf(g_z0);
    float* z1  = symaddrf(g_z1);
    float* s0  = symaddrf(g_s0);
    float* d0  = symaddrf(g_d0);
    float* s1  = symaddrf(g_s1);
    float* d1  = symaddrf(g_d1);
    float* wf01 = symaddrf(g_wf01);
    float* wkl0 = symaddrf(g_wkl0);
    float* wkl1 = symaddrf(g_wkl1);
    int* cnt = symaddri(g_cnt);
    int* cur = symaddri(g_cur);
    int* off = symaddri(g_off);
    int* csr = symaddri(g_csr);

    const int EB = (ET + 255) / 256;
    const int GX = (n + 127) / 128;       // 157 row tiles

    // ===== d: init, then fork CSR build + concat to s2 =====
    init_kernel<<<(4 * n + 255) / 256, 256>>>(cnt, s0, d0, s1, d1);
    cudaEventRecord(g_evA, 0);
    cudaStreamWaitEvent(g_s2, g_evA, 0);

    // ---- s2: CSR build + weight concat (overlaps xw0 GEMM on d) ----
    hist_kernel<<<EB, 256, 0, g_s2>>>(ei, cnt);
    scan_kernel<<<1, 1024, 0, g_s2>>>(cnt, off, cur);
    scatter_kernel<<<EB, 256, 0, g_s2>>>(ei, off, cur, csr);
    concat_kernel<<<128, 256, 0, g_s2>>>(wf01, wkl0, wkl1, gatW1, fcW0, shW0, scW0, shW1, scW1);
    cudaEventRecord(g_evCSR, g_s2);

    // ---- d: xw0 GEMM (mode 4 -> xw0, s0, d0) ----
    gemm_mma_kernel<<<dim3(GX, 4), 256>>>(x, gatW0, n, 256, 1 << 30,
                                          xw0, nullptr, 4, 256,
                                          nullptr, nullptr, 0, 0,
                                          asrc0, adst0, s0, d0, 64);

    // ---- d: join CSR+concat, then layer-0 GAT + fused xw1/z0 GEMM ----
    cudaStreamWaitEvent(0, g_evCSR, 0);
    gat_kernel<64><<<n, 256>>>(csr, off, s0, d0, xw0, gatb0, h0);
    gemm_mma_kernel<<<dim3(GX, 4), 256>>>(h0, wf01, n, 256, 128,
                                          xw1, nullptr, 4, 128,
                                          z0, fcb0, 1, 128,
                                          asrc1, adst1, s1, d1, 32);
    cudaEventRecord(g_evZ0, 0);

    // ---- s2: layer-0 head chain (kl0 -> theta0), overlaps with layer-1 chain on d ----
    cudaStreamWaitEvent(g_s2, g_evZ0, 0);
    gemm_mma_kernel<<<dim3(GX, 4), 256, 0, g_s2>>>(z0, wkl0, n, 128, 128,
                                                   k0, shb0, 2, n,
                                                   l0, scb0, 3, n,
                                                   nullptr, nullptr, nullptr, nullptr, 1);
    theta_kernel<<<(128 * n + 255) / 256, 256, 0, g_s2>>>(k0, l0, eps0, theta0, 128 * n);
    cudaEventRecord(g_evT0, g_s2);

    // ---- d: layer-1 chain (gat1 -> z1 -> kl1 -> theta1) ----
    gat_kernel<32><<<n, 128>>>(csr, off, s1, d1, xw1, gatb1, h1);
    gemm_mma_kernel<<<dim3(GX, 1), 256>>>(h1, fcW1, n, 128, 1 << 30,
                                          z1, fcb1, 1, 64,
                                          nullptr, nullptr, 0, 0,
                                          nullptr, nullptr, nullptr, nullptr, 1);
    gemm_mma_kernel<<<dim3(GX, 2), 256>>>(z1, wkl1, n, 64, 64,
                                          k1, shb1, 2, n,
                                          l1, scb1, 3, n,
                                          nullptr, nullptr, nullptr, nullptr, 1);
    theta_kernel<<<(64 * n + 255) / 256, 256>>>(k1, l1, eps1, theta1, 64 * n);

    // ---- join s2 back into d before return ----
    cudaStreamWaitEvent(0, g_evT0, 0);
}